// round 9
// baseline (speedup 1.0000x reference)
#include <cuda_runtime.h>
#include <cuda_bf16.h>
#include <math.h>
#include <stdint.h>

#define BB 128
#define NN 64
#define DD 64
#define NT 512

typedef unsigned long long u64;

// ---------------- shared memory layout (~204 KB) ----------------
struct SmallS {
    float Qd[128];
    float Xn[NN * 4];
    float Rel[128 * 4];
    float Rd[128];
    float Score[128];
    float Alpha[128];
    float Apart[512];      // u partials (alpha^T kv1)
    float PhxPart[512];    // phx partials from VP fragments
    float W1r0[128];
    float PhxW2[DD];
    float QnW[DD], QnB[DD], KnW[DD], KnB[DD];
    float B1[DD], B2[DD];
    float meanNorm;
};

struct Smem {
    __nv_bfloat16 Ahi[128 * 128];   // 32KB @0      iter: A hi | K fp32 tile after MMA | phase0/2: AREG staging (spans Ahi+Alo)
    __nv_bfloat16 Alo[128 * 128];   // 32KB @32768  iter: A lo
    __nv_bfloat16 Bhi[192 * 128];   // 48KB @65536  rows 0..63: kv_w2 K-cols | 64..127: Wv (A-matvec only) | 128..191: W3
    __nv_bfloat16 Blo[192 * 128];   // 48KB @114688
    float P[NN * 128];              // 32KB
    SmallS sm;
};

#define OFF_AHI 0u
#define OFF_ALO 32768u
#define OFF_BHI 65536u
#define OFF_BLO 114688u

// static device scratch
__device__ float g_A[BB * NN * DD];
__device__ float g_Q[BB * NN * DD];

__device__ __forceinline__ float wredsum(float v) {
#pragma unroll
    for (int o = 16; o > 0; o >>= 1) v += __shfl_xor_sync(0xffffffffu, v, o);
    return v;
}
__device__ __forceinline__ float wredmax(float v) {
#pragma unroll
    for (int o = 16; o > 0; o >>= 1) v = fmaxf(v, __shfl_xor_sync(0xffffffffu, v, o));
    return v;
}
// silu via single-MUFU tanh: silu(x) = 0.5x + 0.5x*tanh(x/2)
__device__ __forceinline__ float silu(float x) {
    float t, hx = 0.5f * x;
    asm("tanh.approx.f32 %0, %1;" : "=f"(t) : "f"(hx));
    return fmaf(hx, t, hx);
}

__device__ __forceinline__ uint32_t smem_u32(const void* p) {
    return (uint32_t)__cvta_generic_to_shared(p);
}
__device__ __forceinline__ uint32_t pack_bf2(float a, float b) {
    __nv_bfloat162 h; h.x = __float2bfloat16(a); h.y = __float2bfloat16(b);
    return *(uint32_t*)&h;
}

// ---- mma.sync / ldmatrix (standard PTX) ----
__device__ __forceinline__ void ldm4(uint32_t* r, uint32_t addr) {
    asm volatile("ldmatrix.sync.aligned.m8n8.x4.shared.b16 {%0,%1,%2,%3}, [%4];"
                 : "=r"(r[0]), "=r"(r[1]), "=r"(r[2]), "=r"(r[3]) : "r"(addr));
}
__device__ __forceinline__ void mma16816(float* d, const uint32_t* a, const uint32_t* b) {
    asm volatile(
        "mma.sync.aligned.m16n8k16.row.col.f32.bf16.bf16.f32 "
        "{%0,%1,%2,%3}, {%4,%5,%6,%7}, {%8,%9}, {%0,%1,%2,%3};"
        : "+f"(d[0]), "+f"(d[1]), "+f"(d[2]), "+f"(d[3])
        : "r"(a[0]), "r"(a[1]), "r"(a[2]), "r"(a[3]), "r"(b[0]), "r"(b[1]));
}

// bf16 tile: row-major, 256B rows, 16B-chunk XOR swizzle
__device__ __forceinline__ uint32_t ABaddr(uint32_t base, int r, int ck) {
    return base + ((uint32_t)r << 8) + ((uint32_t)(ck ^ (r & 7)) << 4);
}
// K fp32 tile: 128 rows x 64 cols, 16B-chunk XOR swizzle
__device__ __forceinline__ int CI64(int r, int c) {
    return (r << 6) + ((((c >> 2) ^ (r & 7)) << 2) | (c & 3));
}

__global__ __launch_bounds__(NT, 1)
void se3_kernel(const float* __restrict__ X, const float* __restrict__ Hg,
                const float* __restrict__ xnw,
                const float* __restrict__ q_w1, const float* __restrict__ q_w2,
                const float* __restrict__ kv_w1, const float* __restrict__ kv_w2,
                const float* __restrict__ qn_w, const float* __restrict__ qn_b,
                const float* __restrict__ kn_w, const float* __restrict__ kn_b,
                const float* __restrict__ phx_w1, const float* __restrict__ phx_w2,
                const float* __restrict__ phh_w1, const float* __restrict__ phh_b1,
                const float* __restrict__ phh_w2, const float* __restrict__ phh_b2,
                float* __restrict__ Xout, float* __restrict__ Hout)
{
    extern __shared__ char smem_raw[];
    Smem& s = *reinterpret_cast<Smem*>(smem_raw);

    const int tid  = threadIdx.x;
    const int lane = tid & 31;
    const int wid  = tid >> 5;
    const int nb   = blockIdx.x * NN;
    const uint32_t sb = smem_u32(smem_raw);

    float* AREG = (float*)s.Ahi;          // 16384 fp32 staging (phase 0/2)
    float* Kf   = (float*)s.Ahi;          // K fp32 tile after MMA (32KB)
    float* Hs   = (float*)s.Bhi;          // 64x64 (phase 0)
    float* T1   = (float*)s.Bhi + 4096;   // 64x64 (phase 0)
    float* Q0   = (float*)s.Blo;          // 64x64 (phase 0)

    // ---------------- phase 0 ----------------
    for (int i = tid; i < NN * DD; i += NT) Hs[i] = Hg[nb * DD + i];
    if (tid < DD) {
        s.sm.QnW[tid] = qn_w[tid];  s.sm.QnB[tid] = qn_b[tid];
        s.sm.KnW[tid] = kn_w[tid];  s.sm.KnB[tid] = kn_b[tid];
        s.sm.PhxW2[tid] = phx_w2[tid];
        s.sm.B1[tid] = phh_b1[tid]; s.sm.B2[tid] = phh_b2[tid];
    }
    if (tid < NN) {
        float x0 = X[(nb + tid) * 3 + 0];
        float x1 = X[(nb + tid) * 3 + 1];
        float x2 = X[(nb + tid) * 3 + 2];
        s.sm.Rd[tid] = sqrtf(x0 * x0 + x1 * x1 + x2 * x2);
        s.sm.Xn[tid * 4 + 0] = x0; s.sm.Xn[tid * 4 + 1] = x1; s.sm.Xn[tid * 4 + 2] = x2;
    }
    for (int i = tid; i < DD * DD; i += NT) AREG[i] = q_w1[i];
    __syncthreads();

    if (tid == 0) {
        float m = 0.f;
        for (int i = 0; i < NN; i++) m += s.sm.Rd[i];
        s.sm.meanNorm = m * (1.f / NN);
    }
    __syncthreads();

    if (tid < NN) {
        float sc = xnw[0] / (s.sm.meanNorm + 1e-5f);
        s.sm.Xn[tid * 4 + 0] *= sc; s.sm.Xn[tid * 4 + 1] *= sc; s.sm.Xn[tid * 4 + 2] *= sc;
    }

    // t1 = silu(H @ q_w1)
    {
        int r0 = wid * 4, j0 = lane * 2;
        float acc[4][2] = {};
#pragma unroll 8
        for (int k = 0; k < DD; k++) {
            float2 bv = *(const float2*)&AREG[k * DD + j0];
#pragma unroll
            for (int i = 0; i < 4; i++) {
                float a = Hs[(r0 + i) * DD + k];
                acc[i][0] += a * bv.x; acc[i][1] += a * bv.y;
            }
        }
#pragma unroll
        for (int i = 0; i < 4; i++) {
            T1[(r0 + i) * DD + j0 + 0] = silu(acc[i][0]);
            T1[(r0 + i) * DD + j0 + 1] = silu(acc[i][1]);
        }
    }
    __syncthreads();
    for (int i = tid; i < DD * DD; i += NT) AREG[i] = q_w2[i];
    __syncthreads();

    // Q0 = t1 @ q_w2
    {
        int r0 = wid * 4, j0 = lane * 2;
        float acc[4][2] = {};
#pragma unroll 8
        for (int k = 0; k < DD; k++) {
            float2 bv = *(const float2*)&AREG[k * DD + j0];
#pragma unroll
            for (int i = 0; i < 4; i++) {
                float a = T1[(r0 + i) * DD + k];
                acc[i][0] += a * bv.x; acc[i][1] += a * bv.y;
            }
        }
#pragma unroll
        for (int i = 0; i < 4; i++) {
            Q0[(r0 + i) * DD + j0 + 0] = acc[i][0];
            Q0[(r0 + i) * DD + j0 + 1] = acc[i][1];
        }
    }
    __syncthreads();

    // LN(Q0) -> g_Q ; stage kv_w1
#pragma unroll
    for (int i = 0; i < 4; i++) {
        int r = wid * 4 + i;
        float v0 = Q0[r * DD + lane], v1 = Q0[r * DD + 32 + lane];
        float sum = wredsum(v0 + v1);
        float sq  = wredsum(v0 * v0 + v1 * v1);
        float mu  = sum * (1.f / DD);
        float var = sq * (1.f / DD) - mu * mu;
        float rstd = rsqrtf(var + 1e-5f);
        g_Q[(nb + r) * DD + lane]      = (v0 - mu) * rstd * s.sm.QnW[lane]      + s.sm.QnB[lane];
        g_Q[(nb + r) * DD + 32 + lane] = (v1 - mu) * rstd * s.sm.QnW[lane + 32] + s.sm.QnB[lane + 32];
    }
    __syncthreads();
    for (int i = tid; i < 65 * 128; i += NT) AREG[i] = kv_w1[i];
    __syncthreads();

    // P = H @ kv_w1[1:,:]
    {
        int r0 = wid * 4, c0 = lane * 4;
        float acc[4][4] = {};
#pragma unroll 8
        for (int k = 0; k < DD; k++) {
            float4 bv = *(const float4*)&AREG[(1 + k) * 128 + c0];
#pragma unroll
            for (int i = 0; i < 4; i++) {
                float a = Hs[(r0 + i) * DD + k];
                acc[i][0] += a * bv.x; acc[i][1] += a * bv.y;
                acc[i][2] += a * bv.z; acc[i][3] += a * bv.w;
            }
        }
#pragma unroll
        for (int i = 0; i < 4; i++)
            *(float4*)&s.P[(r0 + i) * 128 + c0] =
                make_float4(acc[i][0], acc[i][1], acc[i][2], acc[i][3]);
    }
    if (tid < 128) s.sm.W1r0[tid] = AREG[tid];
    __syncthreads();

    // stage kv_w2 fp32 into AREG
    for (int i = tid; i < 128 * 128; i += NT) AREG[i] = kv_w2[i];
    __syncthreads();

    // split kv_w2^T into B rows 0..127 (rows n = output col, k contiguous)
    for (int slot = tid; slot < 2048; slot += NT) {
        int ck = slot >> 7, n = slot & 127;
        uint32_t hi[4], lo[4];
#pragma unroll
        for (int j = 0; j < 4; j++) {
            float x0 = AREG[(ck * 8 + 2 * j) * 128 + n];
            float x1 = AREG[(ck * 8 + 2 * j + 1) * 128 + n];
            __nv_bfloat16 h0 = __float2bfloat16(x0), h1 = __float2bfloat16(x1);
            __nv_bfloat162 hp; hp.x = h0; hp.y = h1;
            hi[j] = *(uint32_t*)&hp;
            lo[j] = pack_bf2(x0 - __bfloat162float(h0), x1 - __bfloat162float(h1));
        }
        *(uint4*)(smem_raw + ABaddr(OFF_BHI, n, ck)) = make_uint4(hi[0], hi[1], hi[2], hi[3]);
        *(uint4*)(smem_raw + ABaddr(OFF_BLO, n, ck)) = make_uint4(lo[0], lo[1], lo[2], lo[3]);
    }
    // W3 = kv_w2[:,64:] @ phx_w1 -> split into B rows 128..191
    for (int slot = tid; slot < 1024; slot += NT) {
        int c = slot >> 4, ck = slot & 15;
        float acc[8] = {0.f, 0.f, 0.f, 0.f, 0.f, 0.f, 0.f, 0.f};
        for (int jj = 0; jj < 64; jj++) {
            int j = (jj + ck * 4) & 63;       // rotate to avoid LDS bank camping
            float w = phx_w1[j * 64 + c];
#pragma unroll
            for (int i = 0; i < 8; i++)
                acc[i] += AREG[(ck * 8 + i) * 128 + 64 + j] * w;
        }
        uint32_t hi[4], lo[4];
#pragma unroll
        for (int j = 0; j < 4; j++) {
            float x0 = acc[2 * j], x1 = acc[2 * j + 1];
            __nv_bfloat16 h0 = __float2bfloat16(x0), h1 = __float2bfloat16(x1);
            __nv_bfloat162 hp; hp.x = h0; hp.y = h1;
            hi[j] = *(uint32_t*)&hp;
            lo[j] = pack_bf2(x0 - __bfloat162float(h0), x1 - __bfloat162float(h1));
        }
        int n = 128 + c;
        *(uint4*)(smem_raw + ABaddr(OFF_BHI, n, ck)) = make_uint4(hi[0], hi[1], hi[2], hi[3]);
        *(uint4*)(smem_raw + ABaddr(OFF_BLO, n, ck)) = make_uint4(lo[0], lo[1], lo[2], lo[3]);
    }
    __syncthreads();

    // ---------------- main loop: 32 iterations, 2 dst nodes each ----------------
    const int r0 = wid * 8;
    const int wm = wid >> 2, wn = wid & 3;
    const int la15 = lane & 15, lhi = lane >> 4, la7 = lane & 7, lb8 = (lane >> 3) & 1;
    const int rA0 = 32 * wm + la15, rA1 = rA0 + 16;
    const int rBK = 16 * wn + lhi * 8 + la7;
    const int rBV = 128 + 16 * wn + lhi * 8 + la7;
    const int rq = lane >> 2, cq = (lane & 3) << 1;

    for (int p = 0; p < 32; p++) {
        const int d0 = 2 * p;

        // 1) rel/rd + Q rows
        if (tid < 128) {
            int r = tid, sIdx = r & 63, dIdx = d0 + (r >> 6);
            float rx = s.sm.Xn[sIdx * 4 + 0] - s.sm.Xn[dIdx * 4 + 0];
            float ry = s.sm.Xn[sIdx * 4 + 1] - s.sm.Xn[dIdx * 4 + 1];
            float rz = s.sm.Xn[sIdx * 4 + 2] - s.sm.Xn[dIdx * 4 + 2];
            s.sm.Rel[r * 4 + 0] = rx; s.sm.Rel[r * 4 + 1] = ry; s.sm.Rel[r * 4 + 2] = rz;
            s.sm.Rd[r] = rx * rx + ry * ry + rz * rz;
            s.sm.Qd[tid] = g_Q[(nb + dIdx) * DD + sIdx];
        }
        __syncthreads();

        // 2) build A = silu(rd*w1row0 + P) as bf16 hi/lo
        for (int slot = tid; slot < 2048; slot += NT) {
            int r = slot >> 4, ck = slot & 15, src = r & 63;
            float rd = s.sm.Rd[r];
            float4 pa = *(const float4*)&s.P[src * 128 + ck * 8];
            float4 pb = *(const float4*)&s.P[src * 128 + ck * 8 + 4];
            float4 wa = *(const float4*)&s.sm.W1r0[ck * 8];
            float4 wb = *(const float4*)&s.sm.W1r0[ck * 8 + 4];
            float v[8];
            v[0] = silu(fmaf(rd, wa.x, pa.x)); v[1] = silu(fmaf(rd, wa.y, pa.y));
            v[2] = silu(fmaf(rd, wa.z, pa.z)); v[3] = silu(fmaf(rd, wa.w, pa.w));
            v[4] = silu(fmaf(rd, wb.x, pb.x)); v[5] = silu(fmaf(rd, wb.y, pb.y));
            v[6] = silu(fmaf(rd, wb.z, pb.z)); v[7] = silu(fmaf(rd, wb.w, pb.w));
            uint32_t hi[4], lo[4];
#pragma unroll
            for (int j = 0; j < 4; j++) {
                float x0 = v[2 * j], x1 = v[2 * j + 1];
                __nv_bfloat16 h0 = __float2bfloat16(x0), h1 = __float2bfloat16(x1);
                __nv_bfloat162 hp; hp.x = h0; hp.y = h1;
                hi[j] = *(uint32_t*)&hp;
                lo[j] = pack_bf2(x0 - __bfloat162float(h0), x1 - __bfloat162float(h1));
            }
            *(uint4*)(smem_raw + ABaddr(OFF_AHI, r, ck)) = make_uint4(hi[0], hi[1], hi[2], hi[3]);
            *(uint4*)(smem_raw + ABaddr(OFF_ALO, r, ck)) = make_uint4(lo[0], lo[1], lo[2], lo[3]);
        }
        __syncthreads();

        // 3) fused MMA: [K | VP] = kv1 @ [Wk | W3], 3-pass bf16 split, 128x128x128
        float accK[16], avp[16];
#pragma unroll
        for (int i = 0; i < 16; i++) { accK[i] = 0.f; avp[i] = 0.f; }
        {
#pragma unroll
            for (int ks = 0; ks < 8; ks++) {
                const int ckA = 2 * ks + lhi, ckB = 2 * ks + lb8;
                uint32_t ah0[4], ah1[4], al0[4], al1[4], bk[4], bv[4];
                ldm4(ah0, ABaddr(sb + OFF_AHI, rA0, ckA));
                ldm4(ah1, ABaddr(sb + OFF_AHI, rA1, ckA));
                ldm4(al0, ABaddr(sb + OFF_ALO, rA0, ckA));
                ldm4(al1, ABaddr(sb + OFF_ALO, rA1, ckA));
                ldm4(bk,  ABaddr(sb + OFF_BHI, rBK, ckB));
                ldm4(bv,  ABaddr(sb + OFF_BHI, rBV, ckB));
#pragma unroll
                for (int j = 0; j < 2; j++) {
                    mma16816(&accK[j * 4],     ah0, bk + j * 2);
                    mma16816(&accK[8 + j * 4], ah1, bk + j * 2);
                    mma16816(&avp[j * 4],      ah0, bv + j * 2);
                    mma16816(&avp[8 + j * 4],  ah1, bv + j * 2);
                    mma16816(&accK[j * 4],     al0, bk + j * 2);
                    mma16816(&accK[8 + j * 4], al1, bk + j * 2);
                    mma16816(&avp[j * 4],      al0, bv + j * 2);
                    mma16816(&avp[8 + j * 4],  al1, bv + j * 2);
                }
                ldm4(bk, ABaddr(sb + OFF_BLO, rBK, ckB));
                ldm4(bv, ABaddr(sb + OFF_BLO, rBV, ckB));
#pragma unroll
                for (int j = 0; j < 2; j++) {
                    mma16816(&accK[j * 4],     ah0, bk + j * 2);
                    mma16816(&accK[8 + j * 4], ah1, bk + j * 2);
                    mma16816(&avp[j * 4],      ah0, bv + j * 2);
                    mma16816(&avp[8 + j * 4],  ah1, bv + j * 2);
                }
            }
        }
        __syncthreads();   // all ldmatrix A reads done before K overwrites Ahi

        // 4) store K fragments (fp32, swizzled) into Ahi region
#pragma unroll
        for (int i = 0; i < 2; i++)
#pragma unroll
            for (int j = 0; j < 2; j++) {
                int r = 32 * wm + 16 * i + rq;
                int c = 16 * wn + 8 * j + cq;
                float* d = &accK[i * 8 + j * 4];
                *(float2*)&Kf[CI64(r, c)]     = make_float2(d[0], d[1]);
                *(float2*)&Kf[CI64(r + 8, c)] = make_float2(d[2], d[3]);
            }
        __syncthreads();

        // 5) LN(K) + score
#pragma unroll
        for (int i = 0; i < 8; i++) {
            int r = r0 + i;
            float k0 = Kf[CI64(r, lane)], k1 = Kf[CI64(r, lane + 32)];
            float sum = wredsum(k0 + k1);
            float sq  = wredsum(k0 * k0 + k1 * k1);
            float mu  = sum * (1.f / DD);
            float var = sq * (1.f / DD) - mu * mu;
            float rstd = rsqrtf(var + 1e-5f);
            float kh0 = (k0 - mu) * rstd * s.sm.KnW[lane]      + s.sm.KnB[lane];
            float kh1 = (k1 - mu) * rstd * s.sm.KnW[lane + 32] + s.sm.KnB[lane + 32];
            int qb = (r >> 6) * DD;
            float dot = wredsum(kh0 * s.sm.Qd[qb + lane] + kh1 * s.sm.Qd[qb + 32 + lane]);
            if (lane == 0) s.sm.Score[r] = dot * 0.125f;
        }
        __syncthreads();

        // 6) softmax (mask self)
        if (wid < 2) {
            int base = wid * 64, dIdx = d0 + wid;
            float s0 = s.sm.Score[base + lane], s1 = s.sm.Score[base + 32 + lane];
            if (lane == dIdx)      s0 = -1e30f;
            if (lane + 32 == dIdx) s1 = -1e30f;
            float m  = wredmax(fmaxf(s0, s1));
            float e0 = __expf(s0 - m), e1 = __expf(s1 - m);
            float ss = wredsum(e0 + e1);
            float inv = __fdividef(1.f, ss);
            s.sm.Alpha[base + lane]      = e0 * inv;
            s.sm.Alpha[base + 32 + lane] = e1 * inv;
        }
        __syncthreads();

        // 7a) u partials: u[dl][k] = sum_e alpha * kv1[e][k] (kv1 recomputed from P)
        {
            int dl = (tid >> 7) & 1, g = tid >> 8, k = tid & 127;
            float w1k = s.sm.W1r0[k];
            float u = 0.f;
            int e0 = g * 32;
#pragma unroll 8
            for (int e = e0; e < e0 + 32; e++) {
                int r = dl * 64 + e;
                u += s.sm.Alpha[r] * silu(fmaf(s.sm.Rd[r], w1k, s.P[e * 128 + k]));
            }
            s.sm.Apart[tid] = u;
        }
        // 7b) phx partials from VP fragments: t = silu(alpha*VP), dot phx_w2
        {
            float w2a[2], w2b[2];
#pragma unroll
            for (int j = 0; j < 2; j++) {
                w2a[j] = s.sm.PhxW2[16 * wn + 8 * j + cq];
                w2b[j] = s.sm.PhxW2[16 * wn + 8 * j + cq + 1];
            }
#pragma unroll
            for (int i = 0; i < 2; i++) {
                int rA = 32 * wm + 16 * i + rq;
                float alA = s.sm.Alpha[rA], alB = s.sm.Alpha[rA + 8];
                float pA = 0.f, pB = 0.f;
#pragma unroll
                for (int j = 0; j < 2; j++) {
                    float* d = &avp[i * 8 + j * 4];
                    pA += silu(alA * d[0]) * w2a[j] + silu(alA * d[1]) * w2b[j];
                    pB += silu(alB * d[2]) * w2a[j] + silu(alB * d[3]) * w2b[j];
                }
                pA += __shfl_xor_sync(0xffffffffu, pA, 1);
                pA += __shfl_xor_sync(0xffffffffu, pA, 2);
                pB += __shfl_xor_sync(0xffffffffu, pB, 1);
                pB += __shfl_xor_sync(0xffffffffu, pB, 2);
                if ((lane & 3) == 0) {
                    s.sm.PhxPart[wn * 128 + rA]     = pA;
                    s.sm.PhxPart[wn * 128 + rA + 8] = pB;
                }
            }
        }
        __syncthreads();

        // 8a) A = u @ Wv  (Wv = kv_w2[:,64:] from B rows 64..127, hi+lo reconstruct)
        {
            int out = tid >> 2, q = tid & 3;
            int dl2 = out >> 6, c = out & 63;
            int n = 64 + c;
            float a = 0.f;
            int k0 = q * 32;
#pragma unroll 8
            for (int k = k0; k < k0 + 32; k++) {
                float uk = s.sm.Apart[dl2 * 128 + k] + s.sm.Apart[256 + dl2 * 128 + k];
                uint32_t off = ABaddr(0u, n, k >> 3) + (uint32_t)(k & 7) * 2u;
                float w = __bfloat162float(*(__nv_bfloat16*)(smem_raw + OFF_BHI + off))
                        + __bfloat162float(*(__nv_bfloat16*)(smem_raw + OFF_BLO + off));
                a += uk * w;
            }
            a += __shfl_xor_sync(0xffffffffu, a, 1);
            a += __shfl_xor_sync(0xffffffffu, a, 2);
            if (q == 0) g_A[(nb + d0 + dl2) * DD + c] = a;
        }
        // 8b) X_out for both dsts
        if (wid < 2) {
            int base = wid * 64, dIdx = d0 + wid;
            float p0 = 0.f, p1 = 0.f, p2 = 0.f;
#pragma unroll
            for (int t2 = 0; t2 < 2; t2++) {
                int r = base + lane + 32 * t2;
                float ph = s.sm.PhxPart[r] + s.sm.PhxPart[128 + r]
                         + s.sm.PhxPart[256 + r] + s.sm.PhxPart[384 + r];
                float wgt = __fdividef(ph, 1.f + sqrtf(s.sm.Rd[r] + 1e-8f));
                p0 += s.sm.Rel[r * 4 + 0] * wgt;
                p1 += s.sm.Rel[r * 4 + 1] * wgt;
                p2 += s.sm.Rel[r * 4 + 2] * wgt;
            }
            p0 = wredsum(p0); p1 = wredsum(p1); p2 = wredsum(p2);
            if (lane == 0) {
                Xout[(nb + dIdx) * 3 + 0] = s.sm.Xn[dIdx * 4 + 0] + p0;
                Xout[(nb + dIdx) * 3 + 1] = s.sm.Xn[dIdx * 4 + 1] + p1;
                Xout[(nb + dIdx) * 3 + 2] = s.sm.Xn[dIdx * 4 + 2] + p2;
            }
        }
        __syncthreads();
    }

    // ---------------- phase 2: H_out ----------------
    float* Mb = (float*)s.Bhi;
    float* Tb = (float*)s.Bhi + 4096;
    for (int i = tid; i < DD * DD; i += NT) AREG[i]        = phh_w1[i];
    for (int i = tid; i < DD * DD; i += NT) AREG[4096 + i] = phh_w2[i];
    __syncthreads();

    // M = A^2 * H
    for (int i = tid; i < NN * DD; i += NT) {
        float a = g_A[nb * DD + i];
        Mb[i] = a * a * Hg[nb * DD + i];
    }
    __syncthreads();

    // t = silu(M @ phh_w1 + b1)
    {
        int rr0 = wid * 4, j0 = lane * 2;
        float acc[4][2] = {};
#pragma unroll 8
        for (int k = 0; k < DD; k++) {
            float2 bv = *(const float2*)&AREG[k * DD + j0];
#pragma unroll
            for (int i = 0; i < 4; i++) {
                float a = Mb[(rr0 + i) * DD + k];
                acc[i][0] += a * bv.x; acc[i][1] += a * bv.y;
            }
        }
#pragma unroll
        for (int i = 0; i < 4; i++) {
            Tb[(rr0 + i) * DD + j0 + 0] = silu(acc[i][0] + s.sm.B1[j0 + 0]);
            Tb[(rr0 + i) * DD + j0 + 1] = silu(acc[i][1] + s.sm.B1[j0 + 1]);
        }
    }
    __syncthreads();

    // H_out = H + t @ phh_w2 + b2
    {
        int rr0 = wid * 4, j0 = lane * 2;
        float acc[4][2] = {};
#pragma unroll 8
        for (int k = 0; k < DD; k++) {
            float2 bv = *(const float2*)&AREG[4096 + k * DD + j0];
#pragma unroll
            for (int i = 0; i < 4; i++) {
                float a = Tb[(rr0 + i) * DD + k];
                acc[i][0] += a * bv.x; acc[i][1] += a * bv.y;
            }
        }
#pragma unroll
        for (int i = 0; i < 4; i++) {
            int n = rr0 + i;
            Hout[(nb + n) * DD + j0 + 0] = Hg[(nb + n) * DD + j0 + 0] + acc[i][0] + s.sm.B2[j0 + 0];
            Hout[(nb + n) * DD + j0 + 1] = Hg[(nb + n) * DD + j0 + 1] + acc[i][1] + s.sm.B2[j0 + 1];
        }
    }
}

extern "C" void kernel_launch(void* const* d_in, const int* in_sizes, int n_in,
                              void* d_out, int out_size)
{
    const float* X      = (const float*)d_in[1];
    const float* Hg     = (const float*)d_in[2];
    const float* xnw    = (const float*)d_in[4];
    const float* q_w1   = (const float*)d_in[5];
    const float* q_w2   = (const float*)d_in[6];
    const float* kv_w1  = (const float*)d_in[7];
    const float* kv_w2  = (const float*)d_in[8];
    const float* qn_w   = (const float*)d_in[9];
    const float* qn_b   = (const float*)d_in[10];
    const float* kn_w   = (const float*)d_in[11];
    const float* kn_b   = (const float*)d_in[12];
    const float* phx_w1 = (const float*)d_in[13];
    const float* phx_w2 = (const float*)d_in[14];
    const float* phh_w1 = (const float*)d_in[15];
    const float* phh_b1 = (const float*)d_in[16];
    const float* phh_w2 = (const float*)d_in[17];
    const float* phh_b2 = (const float*)d_in[18];

    float* out  = (float*)d_out;
    float* Xout = out;
    float* Hout = out + BB * NN * 3;

    cudaFuncSetAttribute(se3_kernel, cudaFuncAttributeMaxDynamicSharedMemorySize,
                         (int)sizeof(Smem));

    se3_kernel<<<BB, NT, sizeof(Smem)>>>(X, Hg, xnw, q_w1, q_w2, kv_w1, kv_w2,
                                         qn_w, qn_b, kn_w, kn_b,
                                         phx_w1, phx_w2,
                                         phh_w1, phh_b1, phh_w2, phh_b2,
                                         Xout, Hout);
}

// round 13
// speedup vs baseline: 1.2253x; 1.2253x over previous
#include <cuda_runtime.h>
#include <cuda_bf16.h>
#include <math.h>
#include <stdint.h>

#define BB 128
#define NN 64
#define DD 64
#define NT 512

typedef unsigned long long u64;

// ---------------- shared memory layout (~181 KB) ----------------
struct SmallS {
    float Qd[2][128];       // parity-buffered Q rows of active dsts
    float Xn[NN * 4];
    float Rel[2][512];
    float Rd[2][128];
    float Alpha[128];
    float Apart[512];       // u partials (alpha^T kv1)
    float PhxPart[512];     // phx partials from VP fragments
    float Spart[12 * 128];  // K row stats partials: [stat(3)*4+wn][row]
    float Wsc[2][2][64];    // parity x dl x col: knw*Qd
    float W1r0[128];
    float PhxW2[DD];
    float QnW[DD], QnB[DD], KnW[DD], KnB[DD];
    float B1[DD], B2[DD];
    float meanNorm;
};

struct Smem {
    __nv_bfloat16 Ahi[128 * 128];   // 32KB @0      iter: A hi | phase0/2: fp32 staging spans Ahi+Alo
    __nv_bfloat16 Alo[128 * 128];   // 32KB @32768
    __nv_bfloat16 Bhi[128 * 128];   // 32KB @65536  rows 0..63: Wk (kv_w2[:, :64]^T) | 64..127: W3
    __nv_bfloat16 Blo[128 * 128];   // 32KB @98304
    float P[NN * 128];              // 32KB
    SmallS sm;
};

#define OFF_AHI 0u
#define OFF_ALO 32768u
#define OFF_BHI 65536u
#define OFF_BLO 98304u

// static device scratch
__device__ float g_A[BB * NN * DD];
__device__ float g_Q[BB * NN * DD];

__device__ __forceinline__ float wredsum(float v) {
#pragma unroll
    for (int o = 16; o > 0; o >>= 1) v += __shfl_xor_sync(0xffffffffu, v, o);
    return v;
}
__device__ __forceinline__ float wredmax(float v) {
#pragma unroll
    for (int o = 16; o > 0; o >>= 1) v = fmaxf(v, __shfl_xor_sync(0xffffffffu, v, o));
    return v;
}
// silu via single-MUFU tanh: silu(x) = 0.5x + 0.5x*tanh(x/2)
__device__ __forceinline__ float silu(float x) {
    float t, hx = 0.5f * x;
    asm("tanh.approx.f32 %0, %1;" : "=f"(t) : "f"(hx));
    return fmaf(hx, t, hx);
}

__device__ __forceinline__ uint32_t smem_u32(const void* p) {
    return (uint32_t)__cvta_generic_to_shared(p);
}
__device__ __forceinline__ uint32_t pack_bf2(float a, float b) {
    __nv_bfloat162 h; h.x = __float2bfloat16(a); h.y = __float2bfloat16(b);
    return *(uint32_t*)&h;
}

// ---- mma.sync / ldmatrix (standard PTX) ----
__device__ __forceinline__ void ldm4(uint32_t* r, uint32_t addr) {
    asm volatile("ldmatrix.sync.aligned.m8n8.x4.shared.b16 {%0,%1,%2,%3}, [%4];"
                 : "=r"(r[0]), "=r"(r[1]), "=r"(r[2]), "=r"(r[3]) : "r"(addr));
}
__device__ __forceinline__ void mma16816(float* d, const uint32_t* a, const uint32_t* b) {
    asm volatile(
        "mma.sync.aligned.m16n8k16.row.col.f32.bf16.bf16.f32 "
        "{%0,%1,%2,%3}, {%4,%5,%6,%7}, {%8,%9}, {%0,%1,%2,%3};"
        : "+f"(d[0]), "+f"(d[1]), "+f"(d[2]), "+f"(d[3])
        : "r"(a[0]), "r"(a[1]), "r"(a[2]), "r"(a[3]), "r"(b[0]), "r"(b[1]));
}

// bf16 tile: row-major, 256B rows, 16B-chunk XOR swizzle
__device__ __forceinline__ uint32_t ABaddr(uint32_t base, int r, int ck) {
    return base + ((uint32_t)r << 8) + ((uint32_t)(ck ^ (r & 7)) << 4);
}

__global__ __launch_bounds__(NT, 1)
void se3_kernel(const float* __restrict__ X, const float* __restrict__ Hg,
                const float* __restrict__ xnw,
                const float* __restrict__ q_w1, const float* __restrict__ q_w2,
                const float* __restrict__ kv_w1, const float* __restrict__ kv_w2,
                const float* __restrict__ qn_w, const float* __restrict__ qn_b,
                const float* __restrict__ kn_w, const float* __restrict__ kn_b,
                const float* __restrict__ phx_w1, const float* __restrict__ phx_w2,
                const float* __restrict__ phh_w1, const float* __restrict__ phh_b1,
                const float* __restrict__ phh_w2, const float* __restrict__ phh_b2,
                float* __restrict__ Xout, float* __restrict__ Hout)
{
    extern __shared__ char smem_raw[];
    Smem& s = *reinterpret_cast<Smem*>(smem_raw);

    const int tid  = threadIdx.x;
    const int lane = tid & 31;
    const int wid  = tid >> 5;
    const int nb   = blockIdx.x * NN;
    const uint32_t sb = smem_u32(smem_raw);

    float* AREG = (float*)s.Ahi;          // 16384 fp32 staging (phase 0/2)
    float* Hs   = (float*)s.Bhi;          // 64x64 (phase 0)
    float* T1   = (float*)s.Bhi + 4096;   // 64x64 (phase 0)
    float* Q0   = (float*)s.Blo;          // 64x64 (phase 0)

    // ---------------- phase 0 ----------------
    for (int i = tid; i < NN * DD; i += NT) Hs[i] = Hg[nb * DD + i];
    if (tid < DD) {
        s.sm.QnW[tid] = qn_w[tid];  s.sm.QnB[tid] = qn_b[tid];
        s.sm.KnW[tid] = kn_w[tid];  s.sm.KnB[tid] = kn_b[tid];
        s.sm.PhxW2[tid] = phx_w2[tid];
        s.sm.B1[tid] = phh_b1[tid]; s.sm.B2[tid] = phh_b2[tid];
    }
    if (tid < NN) {
        float x0 = X[(nb + tid) * 3 + 0];
        float x1 = X[(nb + tid) * 3 + 1];
        float x2 = X[(nb + tid) * 3 + 2];
        s.sm.Rd[0][tid] = sqrtf(x0 * x0 + x1 * x1 + x2 * x2);
        s.sm.Xn[tid * 4 + 0] = x0; s.sm.Xn[tid * 4 + 1] = x1; s.sm.Xn[tid * 4 + 2] = x2;
    }
    for (int i = tid; i < DD * DD; i += NT) AREG[i] = q_w1[i];
    __syncthreads();

    if (tid == 0) {
        float m = 0.f;
        for (int i = 0; i < NN; i++) m += s.sm.Rd[0][i];
        s.sm.meanNorm = m * (1.f / NN);
    }
    __syncthreads();

    if (tid < NN) {
        float sc = xnw[0] / (s.sm.meanNorm + 1e-5f);
        s.sm.Xn[tid * 4 + 0] *= sc; s.sm.Xn[tid * 4 + 1] *= sc; s.sm.Xn[tid * 4 + 2] *= sc;
    }

    // t1 = silu(H @ q_w1)
    {
        int r0 = wid * 4, j0 = lane * 2;
        float acc[4][2] = {};
#pragma unroll 8
        for (int k = 0; k < DD; k++) {
            float2 bv = *(const float2*)&AREG[k * DD + j0];
#pragma unroll
            for (int i = 0; i < 4; i++) {
                float a = Hs[(r0 + i) * DD + k];
                acc[i][0] += a * bv.x; acc[i][1] += a * bv.y;
            }
        }
#pragma unroll
        for (int i = 0; i < 4; i++) {
            T1[(r0 + i) * DD + j0 + 0] = silu(acc[i][0]);
            T1[(r0 + i) * DD + j0 + 1] = silu(acc[i][1]);
        }
    }
    __syncthreads();
    for (int i = tid; i < DD * DD; i += NT) AREG[i] = q_w2[i];
    __syncthreads();

    // Q0 = t1 @ q_w2
    {
        int r0 = wid * 4, j0 = lane * 2;
        float acc[4][2] = {};
#pragma unroll 8
        for (int k = 0; k < DD; k++) {
            float2 bv = *(const float2*)&AREG[k * DD + j0];
#pragma unroll
            for (int i = 0; i < 4; i++) {
                float a = T1[(r0 + i) * DD + k];
                acc[i][0] += a * bv.x; acc[i][1] += a * bv.y;
            }
        }
#pragma unroll
        for (int i = 0; i < 4; i++) {
            Q0[(r0 + i) * DD + j0 + 0] = acc[i][0];
            Q0[(r0 + i) * DD + j0 + 1] = acc[i][1];
        }
    }
    __syncthreads();

    // LN(Q0) -> g_Q ; stage kv_w1
#pragma unroll
    for (int i = 0; i < 4; i++) {
        int r = wid * 4 + i;
        float v0 = Q0[r * DD + lane], v1 = Q0[r * DD + 32 + lane];
        float sum = wredsum(v0 + v1);
        float sq  = wredsum(v0 * v0 + v1 * v1);
        float mu  = sum * (1.f / DD);
        float var = sq * (1.f / DD) - mu * mu;
        float rstd = rsqrtf(var + 1e-5f);
        g_Q[(nb + r) * DD + lane]      = (v0 - mu) * rstd * s.sm.QnW[lane]      + s.sm.QnB[lane];
        g_Q[(nb + r) * DD + 32 + lane] = (v1 - mu) * rstd * s.sm.QnW[lane + 32] + s.sm.QnB[lane + 32];
    }
    __syncthreads();
    for (int i = tid; i < 65 * 128; i += NT) AREG[i] = kv_w1[i];
    __syncthreads();

    // P = H @ kv_w1[1:,:]
    {
        int r0 = wid * 4, c0 = lane * 4;
        float acc[4][4] = {};
#pragma unroll 8
        for (int k = 0; k < DD; k++) {
            float4 bv = *(const float4*)&AREG[(1 + k) * 128 + c0];
#pragma unroll
            for (int i = 0; i < 4; i++) {
                float a = Hs[(r0 + i) * DD + k];
                acc[i][0] += a * bv.x; acc[i][1] += a * bv.y;
                acc[i][2] += a * bv.z; acc[i][3] += a * bv.w;
            }
        }
#pragma unroll
        for (int i = 0; i < 4; i++)
            *(float4*)&s.P[(r0 + i) * 128 + c0] =
                make_float4(acc[i][0], acc[i][1], acc[i][2], acc[i][3]);
    }
    if (tid < 128) s.sm.W1r0[tid] = AREG[tid];
    __syncthreads();

    // stage kv_w2 fp32 into AREG (spans Ahi+Alo, 64KB)
    for (int i = tid; i < 128 * 128; i += NT) AREG[i] = kv_w2[i];
    __syncthreads();

    // split Wk = kv_w2[:, :64]^T into B rows 0..63
    for (int slot = tid; slot < 1024; slot += NT) {
        int ck = slot >> 6, n = slot & 63;
        uint32_t hi[4], lo[4];
#pragma unroll
        for (int j = 0; j < 4; j++) {
            float x0 = AREG[(ck * 8 + 2 * j) * 128 + n];
            float x1 = AREG[(ck * 8 + 2 * j + 1) * 128 + n];
            __nv_bfloat16 h0 = __float2bfloat16(x0), h1 = __float2bfloat16(x1);
            __nv_bfloat162 hp; hp.x = h0; hp.y = h1;
            hi[j] = *(uint32_t*)&hp;
            lo[j] = pack_bf2(x0 - __bfloat162float(h0), x1 - __bfloat162float(h1));
        }
        *(uint4*)(smem_raw + ABaddr(OFF_BHI, n, ck)) = make_uint4(hi[0], hi[1], hi[2], hi[3]);
        *(uint4*)(smem_raw + ABaddr(OFF_BLO, n, ck)) = make_uint4(lo[0], lo[1], lo[2], lo[3]);
    }
    // W3 = kv_w2[:,64:] @ phx_w1 -> split into B rows 64..127
    for (int slot = tid; slot < 1024; slot += NT) {
        int c = slot >> 4, ck = slot & 15;
        float acc[8] = {0.f, 0.f, 0.f, 0.f, 0.f, 0.f, 0.f, 0.f};
        for (int jj = 0; jj < 64; jj++) {
            int j = (jj + ck * 4) & 63;
            float w = phx_w1[j * 64 + c];
#pragma unroll
            for (int i = 0; i < 8; i++)
                acc[i] += AREG[(ck * 8 + i) * 128 + 64 + j] * w;
        }
        uint32_t hi[4], lo[4];
#pragma unroll
        for (int j = 0; j < 4; j++) {
            float x0 = acc[2 * j], x1 = acc[2 * j + 1];
            __nv_bfloat16 h0 = __float2bfloat16(x0), h1 = __float2bfloat16(x1);
            __nv_bfloat162 hp; hp.x = h0; hp.y = h1;
            hi[j] = *(uint32_t*)&hp;
            lo[j] = pack_bf2(x0 - __bfloat162float(h0), x1 - __bfloat162float(h1));
        }
        int n = 64 + c;
        *(uint4*)(smem_raw + ABaddr(OFF_BHI, n, ck)) = make_uint4(hi[0], hi[1], hi[2], hi[3]);
        *(uint4*)(smem_raw + ABaddr(OFF_BLO, n, ck)) = make_uint4(lo[0], lo[1], lo[2], lo[3]);
    }
    __syncthreads();

    // ---------------- main loop: 32 iterations, 2 dst nodes each ----------------
    const int wm = wid >> 2, wn = wid & 3;
    const int dlw = wm >> 1;                       // dst-half of this warp's rows
    const int la15 = lane & 15, lhi = lane >> 4, la7 = lane & 7, lb8 = (lane >> 3) & 1;
    const int rA0 = 32 * wm + la15, rA1 = rA0 + 16;
    const int rBK = 16 * wn + lhi * 8 + la7;
    const int rBV = 64 + 16 * wn + lhi * 8 + la7;
    const int rq = lane >> 2, cq = (lane & 3) << 1;

    for (int p = 0; p < 32; p++) {
        const int d0 = 2 * p;
        const int pb = p & 1;

        // step 1: rel/rd + Q rows + Wsc  (parity-buffered)
        if (tid < 128) {
            int r = tid, sIdx = r & 63, dl = r >> 6, dIdx = d0 + dl;
            float rx = s.sm.Xn[sIdx * 4 + 0] - s.sm.Xn[dIdx * 4 + 0];
            float ry = s.sm.Xn[sIdx * 4 + 1] - s.sm.Xn[dIdx * 4 + 1];
            float rz = s.sm.Xn[sIdx * 4 + 2] - s.sm.Xn[dIdx * 4 + 2];
            s.sm.Rel[pb][r * 4 + 0] = rx; s.sm.Rel[pb][r * 4 + 1] = ry; s.sm.Rel[pb][r * 4 + 2] = rz;
            s.sm.Rd[pb][r] = rx * rx + ry * ry + rz * rz;
            float qv = g_Q[(nb + dIdx) * DD + sIdx];
            s.sm.Qd[pb][r] = qv;
            s.sm.Wsc[pb][dl][sIdx] = s.sm.KnW[sIdx] * qv;
        }
        __syncthreads();   // A

        // step 2: build A = silu(rd*w1row0 + P) as bf16 hi/lo
        for (int slot = tid; slot < 2048; slot += NT) {
            int r = slot >> 4, ck = slot & 15, src = r & 63;
            float rd = s.sm.Rd[pb][r];
            float4 pa = *(const float4*)&s.P[src * 128 + ck * 8];
            float4 pc = *(const float4*)&s.P[src * 128 + ck * 8 + 4];
            float4 wa = *(const float4*)&s.sm.W1r0[ck * 8];
            float4 wb = *(const float4*)&s.sm.W1r0[ck * 8 + 4];
            float v[8];
            v[0] = silu(fmaf(rd, wa.x, pa.x)); v[1] = silu(fmaf(rd, wa.y, pa.y));
            v[2] = silu(fmaf(rd, wa.z, pa.z)); v[3] = silu(fmaf(rd, wa.w, pa.w));
            v[4] = silu(fmaf(rd, wb.x, pc.x)); v[5] = silu(fmaf(rd, wb.y, pc.y));
            v[6] = silu(fmaf(rd, wb.z, pc.z)); v[7] = silu(fmaf(rd, wb.w, pc.w));
            uint32_t hi[4], lo[4];
#pragma unroll
            for (int j = 0; j < 4; j++) {
                float x0 = v[2 * j], x1 = v[2 * j + 1];
                __nv_bfloat16 h0 = __float2bfloat16(x0), h1 = __float2bfloat16(x1);
                __nv_bfloat162 hp; hp.x = h0; hp.y = h1;
                hi[j] = *(uint32_t*)&hp;
                lo[j] = pack_bf2(x0 - __bfloat162float(h0), x1 - __bfloat162float(h1));
            }
            *(uint4*)(smem_raw + ABaddr(OFF_AHI, r, ck)) = make_uint4(hi[0], hi[1], hi[2], hi[3]);
            *(uint4*)(smem_raw + ABaddr(OFF_ALO, r, ck)) = make_uint4(lo[0], lo[1], lo[2], lo[3]);
        }
        __syncthreads();   // B

        // step 3: fused MMA [K | VP], 3-pass bf16 split, 128x128x128
        float accK[16], avp[16];
#pragma unroll
        for (int i = 0; i < 16; i++) { accK[i] = 0.f; avp[i] = 0.f; }
#pragma unroll
        for (int ks = 0; ks < 8; ks++) {
            const int ckA = 2 * ks + lhi, ckB = 2 * ks + lb8;
            uint32_t ah0[4], ah1[4], al0[4], al1[4], bk[4], bv[4];
            ldm4(ah0, ABaddr(sb + OFF_AHI, rA0, ckA));
            ldm4(ah1, ABaddr(sb + OFF_AHI, rA1, ckA));
            ldm4(al0, ABaddr(sb + OFF_ALO, rA0, ckA));
            ldm4(al1, ABaddr(sb + OFF_ALO, rA1, ckA));
            ldm4(bk,  ABaddr(sb + OFF_BHI, rBK, ckB));
            ldm4(bv,  ABaddr(sb + OFF_BHI, rBV, ckB));
#pragma unroll
            for (int j = 0; j < 2; j++) {
                mma16816(&accK[j * 4],     ah0, bk + j * 2);
                mma16816(&accK[8 + j * 4], ah1, bk + j * 2);
                mma16816(&avp[j * 4],      ah0, bv + j * 2);
                mma16816(&avp[8 + j * 4],  ah1, bv + j * 2);
                mma16816(&accK[j * 4],     al0, bk + j * 2);
                mma16816(&accK[8 + j * 4], al1, bk + j * 2);
                mma16816(&avp[j * 4],      al0, bv + j * 2);
                mma16816(&avp[8 + j * 4],  al1, bv + j * 2);
            }
            ldm4(bk, ABaddr(sb + OFF_BLO, rBK, ckB));
            ldm4(bv, ABaddr(sb + OFF_BLO, rBV, ckB));
#pragma unroll
            for (int j = 0; j < 2; j++) {
                mma16816(&accK[j * 4],     ah0, bk + j * 2);
                mma16816(&accK[8 + j * 4], ah1, bk + j * 2);
                mma16816(&avp[j * 4],      ah0, bv + j * 2);
                mma16816(&avp[8 + j * 4],  ah1, bv + j * 2);
            }
        }

        // step 3b: in-register K row stats (sum, sumsq, sum K*w) + quad-reduce
        {
            float w00 = s.sm.Wsc[pb][dlw][16 * wn + cq];
            float w01 = s.sm.Wsc[pb][dlw][16 * wn + cq + 1];
            float w10 = s.sm.Wsc[pb][dlw][16 * wn + 8 + cq];
            float w11 = s.sm.Wsc[pb][dlw][16 * wn + 8 + cq + 1];
#pragma unroll
            for (int i = 0; i < 2; i++)
#pragma unroll
                for (int h = 0; h < 2; h++) {
                    float a0 = accK[i * 8 + 2 * h],     a1 = accK[i * 8 + 2 * h + 1];
                    float b0 = accK[i * 8 + 4 + 2 * h], b1 = accK[i * 8 + 4 + 2 * h + 1];
                    float sK  = (a0 + a1) + (b0 + b1);
                    float sK2 = fmaf(a0, a0, fmaf(a1, a1, fmaf(b0, b0, b1 * b1)));
                    float sKw = fmaf(a0, w00, fmaf(a1, w01, fmaf(b0, w10, b1 * w11)));
                    sK  += __shfl_xor_sync(0xffffffffu, sK, 1);
                    sK  += __shfl_xor_sync(0xffffffffu, sK, 2);
                    sK2 += __shfl_xor_sync(0xffffffffu, sK2, 1);
                    sK2 += __shfl_xor_sync(0xffffffffu, sK2, 2);
                    sKw += __shfl_xor_sync(0xffffffffu, sKw, 1);
                    sKw += __shfl_xor_sync(0xffffffffu, sKw, 2);
                    if ((lane & 3) == 0) {
                        int r = 32 * wm + 16 * i + rq + 8 * h;
                        s.sm.Spart[(0 * 4 + wn) * 128 + r] = sK;
                        s.sm.Spart[(1 * 4 + wn) * 128 + r] = sK2;
                        s.sm.Spart[(2 * 4 + wn) * 128 + r] = sKw;
                    }
                }
        }
        __syncthreads();   // C

        // step 4: score + softmax (2 warps, one per dst)
        if (wid < 2) {
            const int dl = wid, dIdx = d0 + dl;
            float sw  = s.sm.Wsc[pb][dl][lane] + s.sm.Wsc[pb][dl][lane + 32];
            sw = wredsum(sw);
            float sbp = s.sm.KnB[lane]      * s.sm.Qd[pb][dl * 64 + lane]
                      + s.sm.KnB[lane + 32] * s.sm.Qd[pb][dl * 64 + lane + 32];
            sbp = wredsum(sbp);
            const float* Sp = s.sm.Spart;
            float sc[2];
#pragma unroll
            for (int t2 = 0; t2 < 2; t2++) {
                int r = dl * 64 + lane + 32 * t2;
                float sK  = Sp[r]        + Sp[128 + r]  + Sp[256 + r]  + Sp[384 + r];
                float sK2 = Sp[512 + r]  + Sp[640 + r]  + Sp[768 + r]  + Sp[896 + r];
                float sKw = Sp[1024 + r] + Sp[1152 + r] + Sp[1280 + r] + Sp[1408 + r];
                float mu  = sK * (1.f / DD);
                float var = sK2 * (1.f / DD) - mu * mu;
                float rstd = rsqrtf(var + 1e-5f);
                float score = 0.125f * (fmaf(-mu, sw, sKw) * rstd + sbp);
                sc[t2] = (lane + 32 * t2 == dIdx) ? -1e30f : score;
            }
            float m  = wredmax(fmaxf(sc[0], sc[1]));
            float e0 = __expf(sc[0] - m), e1 = __expf(sc[1] - m);
            float ss = wredsum(e0 + e1);
            float inv = __fdividef(1.f, ss);
            s.sm.Alpha[dl * 64 + lane]      = e0 * inv;
            s.sm.Alpha[dl * 64 + 32 + lane] = e1 * inv;
        }
        __syncthreads();   // D

        // step 5a: u partials (alpha^T kv1, kv1 recomputed from P)
        {
            int dl = (tid >> 7) & 1, g = tid >> 8, k = tid & 127;
            float w1k = s.sm.W1r0[k];
            float u = 0.f;
            int e0 = g * 32;
#pragma unroll 8
            for (int e = e0; e < e0 + 32; e++) {
                int r = dl * 64 + e;
                u += s.sm.Alpha[r] * silu(fmaf(s.sm.Rd[pb][r], w1k, s.P[e * 128 + k]));
            }
            s.sm.Apart[tid] = u;
        }
        // step 5b: phx partials from VP fragments
        {
            float w2a[2], w2b[2];
#pragma unroll
            for (int j = 0; j < 2; j++) {
                w2a[j] = s.sm.PhxW2[16 * wn + 8 * j + cq];
                w2b[j] = s.sm.PhxW2[16 * wn + 8 * j + cq + 1];
            }
#pragma unroll
            for (int i = 0; i < 2; i++) {
                int rA = 32 * wm + 16 * i + rq;
                float alA = s.sm.Alpha[rA], alB = s.sm.Alpha[rA + 8];
                float pA = 0.f, pB = 0.f;
#pragma unroll
                for (int j = 0; j < 2; j++) {
                    float* d = &avp[i * 8 + j * 4];
                    pA += silu(alA * d[0]) * w2a[j] + silu(alA * d[1]) * w2b[j];
                    pB += silu(alB * d[2]) * w2a[j] + silu(alB * d[3]) * w2b[j];
                }
                pA += __shfl_xor_sync(0xffffffffu, pA, 1);
                pA += __shfl_xor_sync(0xffffffffu, pA, 2);
                pB += __shfl_xor_sync(0xffffffffu, pB, 1);
                pB += __shfl_xor_sync(0xffffffffu, pB, 2);
                if ((lane & 3) == 0) {
                    s.sm.PhxPart[wn * 128 + rA]     = pA;
                    s.sm.PhxPart[wn * 128 + rA + 8] = pB;
                }
            }
        }
        __syncthreads();   // E

        // step 6a: A = u @ Wv (Wv = kv_w2[:,64:] read fp32 from global/L2)
        {
            int out = tid >> 2, q = tid & 3;
            int dl2 = out >> 6, c = out & 63;
            float a = 0.f;
            int k0 = q * 32;
#pragma unroll 8
            for (int k = k0; k < k0 + 32; k++) {
                float uk = s.sm.Apart[dl2 * 128 + k] + s.sm.Apart[256 + dl2 * 128 + k];
                a += uk * kv_w2[k * 128 + 64 + c];
            }
            a += __shfl_xor_sync(0xffffffffu, a, 1);
            a += __shfl_xor_sync(0xffffffffu, a, 2);
            if (q == 0) g_A[(nb + d0 + dl2) * DD + c] = a;
        }
        // step 6b: X_out for both dsts
        if (wid < 2) {
            int base = wid * 64, dIdx = d0 + wid;
            float p0 = 0.f, p1 = 0.f, p2 = 0.f;
#pragma unroll
            for (int t2 = 0; t2 < 2; t2++) {
                int r = base + lane + 32 * t2;
                float ph = s.sm.PhxPart[r] + s.sm.PhxPart[128 + r]
                         + s.sm.PhxPart[256 + r] + s.sm.PhxPart[384 + r];
                float wgt = __fdividef(ph, 1.f + sqrtf(s.sm.Rd[pb][r] + 1e-8f));
                p0 += s.sm.Rel[pb][r * 4 + 0] * wgt;
                p1 += s.sm.Rel[pb][r * 4 + 1] * wgt;
                p2 += s.sm.Rel[pb][r * 4 + 2] * wgt;
            }
            p0 = wredsum(p0); p1 = wredsum(p1); p2 = wredsum(p2);
            if (lane == 0) {
                Xout[(nb + dIdx) * 3 + 0] = s.sm.Xn[dIdx * 4 + 0] + p0;
                Xout[(nb + dIdx) * 3 + 1] = s.sm.Xn[dIdx * 4 + 1] + p1;
                Xout[(nb + dIdx) * 3 + 2] = s.sm.Xn[dIdx * 4 + 2] + p2;
            }
        }
        // no end barrier: next iter's writes are parity-buffered or behind barriers
    }
    __syncthreads();

    // ---------------- phase 2: H_out ----------------
    float* Mb = (float*)s.Bhi;
    float* Tb = (float*)s.Bhi + 4096;
    for (int i = tid; i < DD * DD; i += NT) AREG[i]        = phh_w1[i];
    for (int i = tid; i < DD * DD; i += NT) AREG[4096 + i] = phh_w2[i];
    __syncthreads();

    // M = A^2 * H
    for (int i = tid; i < NN * DD; i += NT) {
        float a = g_A[nb * DD + i];
        Mb[i] = a * a * Hg[nb * DD + i];
    }
    __syncthreads();

    // t = silu(M @ phh_w1 + b1)
    {
        int rr0 = wid * 4, j0 = lane * 2;
        float acc[4][2] = {};
#pragma unroll 8
        for (int k = 0; k < DD; k++) {
            float2 bv = *(const float2*)&AREG[k * DD + j0];
#pragma unroll
            for (int i = 0; i < 4; i++) {
                float a = Mb[(rr0 + i) * DD + k];
                acc[i][0] += a * bv.x; acc[i][1] += a * bv.y;
            }
        }
#pragma unroll
        for (int i = 0; i < 4; i++) {
            Tb[(rr0 + i) * DD + j0 + 0] = silu(acc[i][0] + s.sm.B1[j0 + 0]);
            Tb[(rr0 + i) * DD + j0 + 1] = silu(acc[i][1] + s.sm.B1[j0 + 1]);
        }
    }
    __syncthreads();

    // H_out = H + t @ phh_w2 + b2
    {
        int rr0 = wid * 4, j0 = lane * 2;
        float acc[4][2] = {};
#pragma unroll 8
        for (int k = 0; k < DD; k++) {
            float2 bv = *(const float2*)&AREG[4096 + k * DD + j0];
#pragma unroll
            for (int i = 0; i < 4; i++) {
                float a = Tb[(rr0 + i) * DD + k];
                acc[i][0] += a * bv.x; acc[i][1] += a * bv.y;
            }
        }
#pragma unroll
        for (int i = 0; i < 4; i++) {
            int n = rr0 + i;
            Hout[(nb + n) * DD + j0 + 0] = Hg[(nb + n) * DD + j0 + 0] + acc[i][0] + s.sm.B2[j0 + 0];
            Hout[(nb + n) * DD + j0 + 1] = Hg[(nb + n) * DD + j0 + 1] + acc[i][1] + s.sm.B2[j0 + 1];
        }
    }
}

extern "C" void kernel_launch(void* const* d_in, const int* in_sizes, int n_in,
                              void* d_out, int out_size)
{
    const float* X      = (const float*)d_in[1];
    const float* Hg     = (const float*)d_in[2];
    const float* xnw    = (const float*)d_in[4];
    const float* q_w1   = (const float*)d_in[5];
    const float* q_w2   = (const float*)d_in[6];
    const float* kv_w1  = (const float*)d_in[7];
    const float* kv_w2  = (const float*)d_in[8];
    const float* qn_w   = (const float*)d_in[9];
    const float* qn_b   = (const float*)d_in[10];
    const float* kn_w   = (const float*)d_in[11];
    const float* kn_b   = (const float*)d_in[12];
    const float* phx_w1 = (const float*)d_in[13];
    const float* phx_w2 = (const float*)d_in[14];
    const float* phh_w1 = (const float*)d_in[15];
    const float* phh_b1 = (const float*)d_in[16];
    const float* phh_w2 = (const float*)d_in[17];
    const float* phh_b2 = (const float*)d_in[18];

    float* out  = (float*)d_out;
    float* Xout = out;
    float* Hout = out + BB * NN * 3;

    cudaFuncSetAttribute(se3_kernel, cudaFuncAttributeMaxDynamicSharedMemorySize,
                         (int)sizeof(Smem));

    se3_kernel<<<BB, NT, sizeof(Smem)>>>(X, Hg, xnw, q_w1, q_w2, kv_w1, kv_w2,
                                         qn_w, qn_b, kn_w, kn_b,
                                         phx_w1, phx_w2,
                                         phh_w1, phh_b1, phh_w2, phh_b2,
                                         Xout, Hout);
}

// round 15
// speedup vs baseline: 1.3185x; 1.0761x over previous
#include <cuda_runtime.h>
#include <cuda_bf16.h>
#include <math.h>
#include <stdint.h>

#define BB 128
#define NN 64
#define DD 64
#define NT 512

typedef unsigned long long u64;

// ---------------- shared memory layout (~192 KB) ----------------
struct SmallS {
    float Qd[2][128];       // parity-buffered Q rows of active dsts
    float Xn[NN * 4];
    float Rdall[NN * NN];   // rel_dist for every (dst,src) pair  [d*64+s]
    float Alpha[128];
    float Apart[512];       // u partials (alpha^T kv1)
    float PhxPart[512];     // phx partials from VP fragments
    float Spart[12 * 128];  // K row stats partials
    float Wsc[2][2][64];    // parity x dl x col: knw*Qd
    float W1r0[128];
    float PhxW2[DD];
    float QnW[DD], QnB[DD], KnW[DD], KnB[DD];
    float B1[DD], B2[DD];
    float meanNorm;
};

struct Smem {
    __nv_bfloat16 Ahi[128 * 128];   // 32KB @0      iter: A hi | phase0/2: fp32 staging spans Ahi+Alo
    __nv_bfloat16 Alo[128 * 128];   // 32KB @32768
    __nv_bfloat16 Bhi[128 * 128];   // 32KB @65536  rows 0..63: Wk | 64..127: W3
    __nv_bfloat16 Blo[128 * 128];   // 32KB @98304
    float P[NN * 128];              // 32KB
    SmallS sm;
};

#define OFF_AHI 0u
#define OFF_ALO 32768u
#define OFF_BHI 65536u
#define OFF_BLO 98304u

// static device scratch
__device__ float g_A[BB * NN * DD];
__device__ float g_Q[BB * NN * DD];

__device__ __forceinline__ float wredsum(float v) {
#pragma unroll
    for (int o = 16; o > 0; o >>= 1) v += __shfl_xor_sync(0xffffffffu, v, o);
    return v;
}
__device__ __forceinline__ float wredmax(float v) {
#pragma unroll
    for (int o = 16; o > 0; o >>= 1) v = fmaxf(v, __shfl_xor_sync(0xffffffffu, v, o));
    return v;
}
// silu via single-MUFU tanh
__device__ __forceinline__ float silu(float x) {
    float t, hx = 0.5f * x;
    asm("tanh.approx.f32 %0, %1;" : "=f"(t) : "f"(hx));
    return fmaf(hx, t, hx);
}

__device__ __forceinline__ uint32_t smem_u32(const void* p) {
    return (uint32_t)__cvta_generic_to_shared(p);
}
__device__ __forceinline__ uint32_t pack_bf2(float a, float b) {
    __nv_bfloat162 h; h.x = __float2bfloat16(a); h.y = __float2bfloat16(b);
    return *(uint32_t*)&h;
}

// ---- mma.sync / ldmatrix (standard PTX) ----
__device__ __forceinline__ void ldm4(uint32_t* r, uint32_t addr) {
    asm volatile("ldmatrix.sync.aligned.m8n8.x4.shared.b16 {%0,%1,%2,%3}, [%4];"
                 : "=r"(r[0]), "=r"(r[1]), "=r"(r[2]), "=r"(r[3]) : "r"(addr));
}
__device__ __forceinline__ void mma16816(float* d, const uint32_t* a, const uint32_t* b) {
    asm volatile(
        "mma.sync.aligned.m16n8k16.row.col.f32.bf16.bf16.f32 "
        "{%0,%1,%2,%3}, {%4,%5,%6,%7}, {%8,%9}, {%0,%1,%2,%3};"
        : "+f"(d[0]), "+f"(d[1]), "+f"(d[2]), "+f"(d[3])
        : "r"(a[0]), "r"(a[1]), "r"(a[2]), "r"(a[3]), "r"(b[0]), "r"(b[1]));
}

// bf16 tile: row-major, 256B rows, 16B-chunk XOR swizzle
__device__ __forceinline__ uint32_t ABaddr(uint32_t base, int r, int ck) {
    return base + ((uint32_t)r << 8) + ((uint32_t)(ck ^ (r & 7)) << 4);
}

// build A = silu(rd*w1row0 + P) as bf16 hi/lo for dst pair d0n, slots [slot0::stride)
__device__ __forceinline__ void build_A(char* smem_raw, SmallS& sm, const float* P,
                                        int d0n, int slot0, int stride) {
    for (int slot = slot0; slot < 2048; slot += stride) {
        int r = slot >> 4, ck = slot & 15, src = r & 63;
        float rd = sm.Rdall[(d0n + (r >> 6)) * 64 + src];
        float4 pa = *(const float4*)&P[src * 128 + ck * 8];
        float4 pc = *(const float4*)&P[src * 128 + ck * 8 + 4];
        float4 wa = *(const float4*)&sm.W1r0[ck * 8];
        float4 wb = *(const float4*)&sm.W1r0[ck * 8 + 4];
        float v[8];
        v[0] = silu(fmaf(rd, wa.x, pa.x)); v[1] = silu(fmaf(rd, wa.y, pa.y));
        v[2] = silu(fmaf(rd, wa.z, pa.z)); v[3] = silu(fmaf(rd, wa.w, pa.w));
        v[4] = silu(fmaf(rd, wb.x, pc.x)); v[5] = silu(fmaf(rd, wb.y, pc.y));
        v[6] = silu(fmaf(rd, wb.z, pc.z)); v[7] = silu(fmaf(rd, wb.w, pc.w));
        uint32_t hi[4], lo[4];
#pragma unroll
        for (int j = 0; j < 4; j++) {
            float x0 = v[2 * j], x1 = v[2 * j + 1];
            __nv_bfloat16 h0 = __float2bfloat16(x0), h1 = __float2bfloat16(x1);
            __nv_bfloat162 hp; hp.x = h0; hp.y = h1;
            hi[j] = *(uint32_t*)&hp;
            lo[j] = pack_bf2(x0 - __bfloat162float(h0), x1 - __bfloat162float(h1));
        }
        *(uint4*)(smem_raw + ABaddr(OFF_AHI, r, ck)) = make_uint4(hi[0], hi[1], hi[2], hi[3]);
        *(uint4*)(smem_raw + ABaddr(OFF_ALO, r, ck)) = make_uint4(lo[0], lo[1], lo[2], lo[3]);
    }
}

__global__ __launch_bounds__(NT, 1)
void se3_kernel(const float* __restrict__ X, const float* __restrict__ Hg,
                const float* __restrict__ xnw,
                const float* __restrict__ q_w1, const float* __restrict__ q_w2,
                const float* __restrict__ kv_w1, const float* __restrict__ kv_w2,
                const float* __restrict__ qn_w, const float* __restrict__ qn_b,
                const float* __restrict__ kn_w, const float* __restrict__ kn_b,
                const float* __restrict__ phx_w1, const float* __restrict__ phx_w2,
                const float* __restrict__ phh_w1, const float* __restrict__ phh_b1,
                const float* __restrict__ phh_w2, const float* __restrict__ phh_b2,
                float* __restrict__ Xout, float* __restrict__ Hout)
{
    extern __shared__ char smem_raw[];
    Smem& s = *reinterpret_cast<Smem*>(smem_raw);

    const int tid  = threadIdx.x;
    const int lane = tid & 31;
    const int wid  = tid >> 5;
    const int nb   = blockIdx.x * NN;
    const uint32_t sb = smem_u32(smem_raw);

    float* AREG = (float*)s.Ahi;          // 16384 fp32 staging (phase 0/2)
    float* Hs   = (float*)s.Bhi;          // 64x64 (phase 0)
    float* T1   = (float*)s.Bhi + 4096;   // 64x64 (phase 0)
    float* Q0   = (float*)s.Blo;          // 64x64 (phase 0)

    // ---------------- phase 0 ----------------
    for (int i = tid; i < NN * DD; i += NT) Hs[i] = Hg[nb * DD + i];
    if (tid < DD) {
        s.sm.QnW[tid] = qn_w[tid];  s.sm.QnB[tid] = qn_b[tid];
        s.sm.KnW[tid] = kn_w[tid];  s.sm.KnB[tid] = kn_b[tid];
        s.sm.PhxW2[tid] = phx_w2[tid];
        s.sm.B1[tid] = phh_b1[tid]; s.sm.B2[tid] = phh_b2[tid];
    }
    if (tid < NN) {
        float x0 = X[(nb + tid) * 3 + 0];
        float x1 = X[(nb + tid) * 3 + 1];
        float x2 = X[(nb + tid) * 3 + 2];
        s.sm.Rdall[tid] = sqrtf(x0 * x0 + x1 * x1 + x2 * x2);   // temp: norms
        s.sm.Xn[tid * 4 + 0] = x0; s.sm.Xn[tid * 4 + 1] = x1; s.sm.Xn[tid * 4 + 2] = x2;
    }
    for (int i = tid; i < DD * DD; i += NT) AREG[i] = q_w1[i];
    __syncthreads();

    if (tid == 0) {
        float m = 0.f;
        for (int i = 0; i < NN; i++) m += s.sm.Rdall[i];
        s.sm.meanNorm = m * (1.f / NN);
    }
    __syncthreads();

    if (tid < NN) {
        float sc = xnw[0] / (s.sm.meanNorm + 1e-5f);
        s.sm.Xn[tid * 4 + 0] *= sc; s.sm.Xn[tid * 4 + 1] *= sc; s.sm.Xn[tid * 4 + 2] *= sc;
    }

    // t1 = silu(H @ q_w1)
    {
        int r0 = wid * 4, j0 = lane * 2;
        float acc[4][2] = {};
#pragma unroll 8
        for (int k = 0; k < DD; k++) {
            float2 bv = *(const float2*)&AREG[k * DD + j0];
#pragma unroll
            for (int i = 0; i < 4; i++) {
                float a = Hs[(r0 + i) * DD + k];
                acc[i][0] += a * bv.x; acc[i][1] += a * bv.y;
            }
        }
#pragma unroll
        for (int i = 0; i < 4; i++) {
            T1[(r0 + i) * DD + j0 + 0] = silu(acc[i][0]);
            T1[(r0 + i) * DD + j0 + 1] = silu(acc[i][1]);
        }
    }
    __syncthreads();
    for (int i = tid; i < DD * DD; i += NT) AREG[i] = q_w2[i];
    // Rdall: full 64x64 rel_dist matrix (Xn final after barrier above)
    for (int idx = tid; idx < NN * NN; idx += NT) {
        int d = idx >> 6, sc2 = idx & 63;
        float rx = s.sm.Xn[sc2 * 4 + 0] - s.sm.Xn[d * 4 + 0];
        float ry = s.sm.Xn[sc2 * 4 + 1] - s.sm.Xn[d * 4 + 1];
        float rz = s.sm.Xn[sc2 * 4 + 2] - s.sm.Xn[d * 4 + 2];
        s.sm.Rdall[idx] = rx * rx + ry * ry + rz * rz;
    }
    __syncthreads();

    // Q0 = t1 @ q_w2
    {
        int r0 = wid * 4, j0 = lane * 2;
        float acc[4][2] = {};
#pragma unroll 8
        for (int k = 0; k < DD; k++) {
            float2 bv = *(const float2*)&AREG[k * DD + j0];
#pragma unroll
            for (int i = 0; i < 4; i++) {
                float a = T1[(r0 + i) * DD + k];
                acc[i][0] += a * bv.x; acc[i][1] += a * bv.y;
            }
        }
#pragma unroll
        for (int i = 0; i < 4; i++) {
            Q0[(r0 + i) * DD + j0 + 0] = acc[i][0];
            Q0[(r0 + i) * DD + j0 + 1] = acc[i][1];
        }
    }
    __syncthreads();

    // LN(Q0) -> g_Q ; stage kv_w1
#pragma unroll
    for (int i = 0; i < 4; i++) {
        int r = wid * 4 + i;
        float v0 = Q0[r * DD + lane], v1 = Q0[r * DD + 32 + lane];
        float sum = wredsum(v0 + v1);
        float sq  = wredsum(v0 * v0 + v1 * v1);
        float mu  = sum * (1.f / DD);
        float var = sq * (1.f / DD) - mu * mu;
        float rstd = rsqrtf(var + 1e-5f);
        g_Q[(nb + r) * DD + lane]      = (v0 - mu) * rstd * s.sm.QnW[lane]      + s.sm.QnB[lane];
        g_Q[(nb + r) * DD + 32 + lane] = (v1 - mu) * rstd * s.sm.QnW[lane + 32] + s.sm.QnB[lane + 32];
    }
    __syncthreads();
    for (int i = tid; i < 65 * 128; i += NT) AREG[i] = kv_w1[i];
    __syncthreads();

    // P = H @ kv_w1[1:,:]
    {
        int r0 = wid * 4, c0 = lane * 4;
        float acc[4][4] = {};
#pragma unroll 8
        for (int k = 0; k < DD; k++) {
            float4 bv = *(const float4*)&AREG[(1 + k) * 128 + c0];
#pragma unroll
            for (int i = 0; i < 4; i++) {
                float a = Hs[(r0 + i) * DD + k];
                acc[i][0] += a * bv.x; acc[i][1] += a * bv.y;
                acc[i][2] += a * bv.z; acc[i][3] += a * bv.w;
            }
        }
#pragma unroll
        for (int i = 0; i < 4; i++)
            *(float4*)&s.P[(r0 + i) * 128 + c0] =
                make_float4(acc[i][0], acc[i][1], acc[i][2], acc[i][3]);
    }
    if (tid < 128) s.sm.W1r0[tid] = AREG[tid];
    __syncthreads();

    // stage kv_w2 fp32 into AREG (spans Ahi+Alo, 64KB)
    for (int i = tid; i < 128 * 128; i += NT) AREG[i] = kv_w2[i];
    __syncthreads();

    // split Wk = kv_w2[:, :64]^T into B rows 0..63
    for (int slot = tid; slot < 1024; slot += NT) {
        int ck = slot >> 6, n = slot & 63;
        uint32_t hi[4], lo[4];
#pragma unroll
        for (int j = 0; j < 4; j++) {
            float x0 = AREG[(ck * 8 + 2 * j) * 128 + n];
            float x1 = AREG[(ck * 8 + 2 * j + 1) * 128 + n];
            __nv_bfloat16 h0 = __float2bfloat16(x0), h1 = __float2bfloat16(x1);
            __nv_bfloat162 hp; hp.x = h0; hp.y = h1;
            hi[j] = *(uint32_t*)&hp;
            lo[j] = pack_bf2(x0 - __bfloat162float(h0), x1 - __bfloat162float(h1));
        }
        *(uint4*)(smem_raw + ABaddr(OFF_BHI, n, ck)) = make_uint4(hi[0], hi[1], hi[2], hi[3]);
        *(uint4*)(smem_raw + ABaddr(OFF_BLO, n, ck)) = make_uint4(lo[0], lo[1], lo[2], lo[3]);
    }
    // W3 = kv_w2[:,64:] @ phx_w1 -> split into B rows 64..127
    for (int slot = tid; slot < 1024; slot += NT) {
        int c = slot >> 4, ck = slot & 15;
        float acc[8] = {0.f, 0.f, 0.f, 0.f, 0.f, 0.f, 0.f, 0.f};
        for (int jj = 0; jj < 64; jj++) {
            int j = (jj + ck * 4) & 63;
            float w = phx_w1[j * 64 + c];
#pragma unroll
            for (int i = 0; i < 8; i++)
                acc[i] += AREG[(ck * 8 + i) * 128 + 64 + j] * w;
        }
        uint32_t hi[4], lo[4];
#pragma unroll
        for (int j = 0; j < 4; j++) {
            float x0 = acc[2 * j], x1 = acc[2 * j + 1];
            __nv_bfloat16 h0 = __float2bfloat16(x0), h1 = __float2bfloat16(x1);
            __nv_bfloat162 hp; hp.x = h0; hp.y = h1;
            hi[j] = *(uint32_t*)&hp;
            lo[j] = pack_bf2(x0 - __bfloat162float(h0), x1 - __bfloat162float(h1));
        }
        int n = 64 + c;
        *(uint4*)(smem_raw + ABaddr(OFF_BHI, n, ck)) = make_uint4(hi[0], hi[1], hi[2], hi[3]);
        *(uint4*)(smem_raw + ABaddr(OFF_BLO, n, ck)) = make_uint4(lo[0], lo[1], lo[2], lo[3]);
    }
    __syncthreads();

    // prologue: Qd/Wsc for p=0 + A tiles for p=0
    if (tid < 128) {
        int r = tid, sIdx = r & 63, dl = r >> 6;
        float qv = g_Q[(nb + dl) * DD + sIdx];
        s.sm.Qd[0][r] = qv;
        s.sm.Wsc[0][dl][sIdx] = s.sm.KnW[sIdx] * qv;
    }
    build_A(smem_raw, s.sm, s.P, 0, tid, NT);
    __syncthreads();

    // ---------------- main loop: 32 iterations, 2 dst nodes each ----------------
    const int wm = wid >> 2, wn = wid & 3;
    const int dlw = wm >> 1;
    const int la15 = lane & 15, lhi = lane >> 4, la7 = lane & 7, lb8 = (lane >> 3) & 1;
    const int rA0 = 32 * wm + la15, rA1 = rA0 + 16;
    const int rBK = 16 * wn + lhi * 8 + la7;
    const int rBV = 64 + 16 * wn + lhi * 8 + la7;
    const int rq = lane >> 2, cq = (lane & 3) << 1;

    for (int p = 0; p < 32; p++) {
        const int d0 = 2 * p;
        const int pb = p & 1;

        // step 3: fused MMA [K | VP], 3-pass bf16 split, 128x128x128
        float accK[16], avp[16];
#pragma unroll
        for (int i = 0; i < 16; i++) { accK[i] = 0.f; avp[i] = 0.f; }
#pragma unroll
        for (int ks = 0; ks < 8; ks++) {
            const int ckA = 2 * ks + lhi, ckB = 2 * ks + lb8;
            uint32_t ah0[4], ah1[4], al0[4], al1[4], bk[4], bv[4];
            ldm4(ah0, ABaddr(sb + OFF_AHI, rA0, ckA));
            ldm4(ah1, ABaddr(sb + OFF_AHI, rA1, ckA));
            ldm4(al0, ABaddr(sb + OFF_ALO, rA0, ckA));
            ldm4(al1, ABaddr(sb + OFF_ALO, rA1, ckA));
            ldm4(bk,  ABaddr(sb + OFF_BHI, rBK, ckB));
            ldm4(bv,  ABaddr(sb + OFF_BHI, rBV, ckB));
#pragma unroll
            for (int j = 0; j < 2; j++) {
                mma16816(&accK[j * 4],     ah0, bk + j * 2);
                mma16816(&accK[8 + j * 4], ah1, bk + j * 2);
                mma16816(&avp[j * 4],      ah0, bv + j * 2);
                mma16816(&avp[8 + j * 4],  ah1, bv + j * 2);
                mma16816(&accK[j * 4],     al0, bk + j * 2);
                mma16816(&accK[8 + j * 4], al1, bk + j * 2);
                mma16816(&avp[j * 4],      al0, bv + j * 2);
                mma16816(&avp[8 + j * 4],  al1, bv + j * 2);
            }
            ldm4(bk, ABaddr(sb + OFF_BLO, rBK, ckB));
            ldm4(bv, ABaddr(sb + OFF_BLO, rBV, ckB));
#pragma unroll
            for (int j = 0; j < 2; j++) {
                mma16816(&accK[j * 4],     ah0, bk + j * 2);
                mma16816(&accK[8 + j * 4], ah1, bk + j * 2);
                mma16816(&avp[j * 4],      ah0, bv + j * 2);
                mma16816(&avp[8 + j * 4],  ah1, bv + j * 2);
            }
        }

        // step 3b: in-register K row stats + quad-reduce
        {
            float w00 = s.sm.Wsc[pb][dlw][16 * wn + cq];
            float w01 = s.sm.Wsc[pb][dlw][16 * wn + cq + 1];
            float w10 = s.sm.Wsc[pb][dlw][16 * wn + 8 + cq];
            float w11 = s.sm.Wsc[pb][dlw][16 * wn + 8 + cq + 1];
#pragma unroll
            for (int i = 0; i < 2; i++)
#pragma unroll
                for (int h = 0; h < 2; h++) {
                    float a0 = accK[i * 8 + 2 * h],     a1 = accK[i * 8 + 2 * h + 1];
                    float b0 = accK[i * 8 + 4 + 2 * h], b1 = accK[i * 8 + 4 + 2 * h + 1];
                    float sK  = (a0 + a1) + (b0 + b1);
                    float sK2 = fmaf(a0, a0, fmaf(a1, a1, fmaf(b0, b0, b1 * b1)));
                    float sKw = fmaf(a0, w00, fmaf(a1, w01, fmaf(b0, w10, b1 * w11)));
                    sK  += __shfl_xor_sync(0xffffffffu, sK, 1);
                    sK  += __shfl_xor_sync(0xffffffffu, sK, 2);
                    sK2 += __shfl_xor_sync(0xffffffffu, sK2, 1);
                    sK2 += __shfl_xor_sync(0xffffffffu, sK2, 2);
                    sKw += __shfl_xor_sync(0xffffffffu, sKw, 1);
                    sKw += __shfl_xor_sync(0xffffffffu, sKw, 2);
                    if ((lane & 3) == 0) {
                        int r = 32 * wm + 16 * i + rq + 8 * h;
                        s.sm.Spart[(0 * 4 + wn) * 128 + r] = sK;
                        s.sm.Spart[(1 * 4 + wn) * 128 + r] = sK2;
                        s.sm.Spart[(2 * 4 + wn) * 128 + r] = sKw;
                    }
                }
        }
        __syncthreads();   // C: Spart visible; A tiles free for rebuild

        // step 4: warps 0-1 softmax; warps 2-15 build next iteration's A tiles
        if (wid < 2) {
            const int dl = wid, dIdx = d0 + dl;
            float sw  = s.sm.Wsc[pb][dl][lane] + s.sm.Wsc[pb][dl][lane + 32];
            sw = wredsum(sw);
            float sbp = s.sm.KnB[lane]      * s.sm.Qd[pb][dl * 64 + lane]
                      + s.sm.KnB[lane + 32] * s.sm.Qd[pb][dl * 64 + lane + 32];
            sbp = wredsum(sbp);
            const float* Sp = s.sm.Spart;
            float sc[2];
#pragma unroll
            for (int t2 = 0; t2 < 2; t2++) {
                int r = dl * 64 + lane + 32 * t2;
                float sK  = Sp[r]        + Sp[128 + r]  + Sp[256 + r]  + Sp[384 + r];
                float sK2 = Sp[512 + r]  + Sp[640 + r]  + Sp[768 + r]  + Sp[896 + r];
                float sKw = Sp[1024 + r] + Sp[1152 + r] + Sp[1280 + r] + Sp[1408 + r];
                float mu  = sK * (1.f / DD);
                float var = sK2 * (1.f / DD) - mu * mu;
                float rstd = rsqrtf(var + 1e-5f);
                float score = 0.125f * (fmaf(-mu, sw, sKw) * rstd + sbp);
                sc[t2] = (lane + 32 * t2 == dIdx) ? -1e30f : score;
            }
            float m  = wredmax(fmaxf(sc[0], sc[1]));
            float e0 = __expf(sc[0] - m), e1 = __expf(sc[1] - m);
            float ss = wredsum(e0 + e1);
            float inv = __fdividef(1.f, ss);
            s.sm.Alpha[dl * 64 + lane]      = e0 * inv;
            s.sm.Alpha[dl * 64 + 32 + lane] = e1 * inv;
        } else if (p < 31) {
            build_A(smem_raw, s.sm, s.P, d0 + 2, tid - 64, NT - 64);
        }
        __syncthreads();   // D: Alpha + next A tiles ready

        // step 5a: u partials (alpha^T kv1, kv1 recomputed from P)
        {
            int dl = (tid >> 7) & 1, g = tid >> 8, k = tid & 127;
            float w1k = s.sm.W1r0[k];
            const float* rdrow = &s.sm.Rdall[(d0 + dl) * 64];
            float u = 0.f;
            int e0 = g * 32;
#pragma unroll 8
            for (int e = e0; e < e0 + 32; e++) {
                u += s.sm.Alpha[dl * 64 + e] * silu(fmaf(rdrow[e], w1k, s.P[e * 128 + k]));
            }
            s.sm.Apart[tid] = u;
        }
        // step 5b: phx partials from VP fragments
        {
            float w2a[2], w2b[2];
#pragma unroll
            for (int j = 0; j < 2; j++) {
                w2a[j] = s.sm.PhxW2[16 * wn + 8 * j + cq];
                w2b[j] = s.sm.PhxW2[16 * wn + 8 * j + cq + 1];
            }
#pragma unroll
            for (int i = 0; i < 2; i++) {
                int rA = 32 * wm + 16 * i + rq;
                float alA = s.sm.Alpha[rA], alB = s.sm.Alpha[rA + 8];
                float pA = 0.f, pB = 0.f;
#pragma unroll
                for (int j = 0; j < 2; j++) {
                    float* d = &avp[i * 8 + j * 4];
                    pA += silu(alA * d[0]) * w2a[j] + silu(alA * d[1]) * w2b[j];
                    pB += silu(alB * d[2]) * w2a[j] + silu(alB * d[3]) * w2b[j];
                }
                pA += __shfl_xor_sync(0xffffffffu, pA, 1);
                pA += __shfl_xor_sync(0xffffffffu, pA, 2);
                pB += __shfl_xor_sync(0xffffffffu, pB, 1);
                pB += __shfl_xor_sync(0xffffffffu, pB, 2);
                if ((lane & 3) == 0) {
                    s.sm.PhxPart[wn * 128 + rA]     = pA;
                    s.sm.PhxPart[wn * 128 + rA + 8] = pB;
                }
            }
        }
        // step 5c: prefetch Qd/Wsc for next pair (parity buffer)
        if (p < 31 && tid < 128) {
            int r = tid, sIdx = r & 63, dl = r >> 6, dIdx = d0 + 2 + dl;
            float qv = g_Q[(nb + dIdx) * DD + sIdx];
            s.sm.Qd[pb ^ 1][r] = qv;
            s.sm.Wsc[pb ^ 1][dl][sIdx] = s.sm.KnW[sIdx] * qv;
        }
        __syncthreads();   // E

        // step 6a: A = u @ Wv (kv_w2[:,64:] fp32 from L2)
        {
            int out = tid >> 2, q = tid & 3;
            int dl2 = out >> 6, c = out & 63;
            float a = 0.f;
            int k0 = q * 32;
#pragma unroll 8
            for (int k = k0; k < k0 + 32; k++) {
                float uk = s.sm.Apart[dl2 * 128 + k] + s.sm.Apart[256 + dl2 * 128 + k];
                a += uk * kv_w2[k * 128 + 64 + c];
            }
            a += __shfl_xor_sync(0xffffffffu, a, 1);
            a += __shfl_xor_sync(0xffffffffu, a, 2);
            if (q == 0) g_A[(nb + d0 + dl2) * DD + c] = a;
        }
        // step 6b: X_out for both dsts (Rel recomputed from Xn)
        if (wid < 2) {
            int base = wid * 64, dIdx = d0 + wid;
            float dx = s.sm.Xn[dIdx * 4 + 0], dy = s.sm.Xn[dIdx * 4 + 1], dz = s.sm.Xn[dIdx * 4 + 2];
            float p0 = 0.f, p1 = 0.f, p2 = 0.f;
#pragma unroll
            for (int t2 = 0; t2 < 2; t2++) {
                int r = base + lane + 32 * t2, src = (lane + 32 * t2);
                float ph = s.sm.PhxPart[r] + s.sm.PhxPart[128 + r]
                         + s.sm.PhxPart[256 + r] + s.sm.PhxPart[384 + r];
                float rd = s.sm.Rdall[dIdx * 64 + src];
                float wgt = __fdividef(ph, 1.f + sqrtf(rd + 1e-8f));
                p0 += (s.sm.Xn[src * 4 + 0] - dx) * wgt;
                p1 += (s.sm.Xn[src * 4 + 1] - dy) * wgt;
                p2 += (s.sm.Xn[src * 4 + 2] - dz) * wgt;
            }
            p0 = wredsum(p0); p1 = wredsum(p1); p2 = wredsum(p2);
            if (lane == 0) {
                Xout[(nb + dIdx) * 3 + 0] = dx + p0;
                Xout[(nb + dIdx) * 3 + 1] = dy + p1;
                Xout[(nb + dIdx) * 3 + 2] = dz + p2;
            }
        }
        // no end barrier: next-iter smem writes are behind barriers C/D/E
    }
    __syncthreads();

    // ---------------- phase 2: H_out ----------------
    float* Mb = (float*)s.Bhi;
    float* Tb = (float*)s.Bhi + 4096;
    for (int i = tid; i < DD * DD; i += NT) AREG[i]        = phh_w1[i];
    for (int i = tid; i < DD * DD; i += NT) AREG[4096 + i] = phh_w2[i];
    __syncthreads();

    // M = A^2 * H
    for (int i = tid; i < NN * DD; i += NT) {
        float a = g_A[nb * DD + i];
        Mb[i] = a * a * Hg[nb * DD + i];
    }
    __syncthreads();

    // t = silu(M @ phh_w1 + b1)
    {
        int rr0 = wid * 4, j0 = lane * 2;
        float acc[4][2] = {};
#pragma unroll 8
        for (int k = 0; k < DD; k++) {
            float2 bv = *(const float2*)&AREG[k * DD + j0];
#pragma unroll
            for (int i = 0; i < 4; i++) {
                float a = Mb[(rr0 + i) * DD + k];
                acc[i][0] += a * bv.x; acc[i][1] += a * bv.y;
            }
        }
#pragma unroll
        for (int i = 0; i < 4; i++) {
            Tb[(rr0 + i) * DD + j0 + 0] = silu(acc[i][0] + s.sm.B1[j0 + 0]);
            Tb[(rr0 + i) * DD + j0 + 1] = silu(acc[i][1] + s.sm.B1[j0 + 1]);
        }
    }
    __syncthreads();

    // H_out = H + t @ phh_w2 + b2
    {
        int rr0 = wid * 4, j0 = lane * 2;
        float acc[4][2] = {};
#pragma unroll 8
        for (int k = 0; k < DD; k++) {
            float2 bv = *(const float2*)&AREG[4096 + k * DD + j0];
#pragma unroll
            for (int i = 0; i < 4; i++) {
                float a = Tb[(rr0 + i) * DD + k];
                acc[i][0] += a * bv.x; acc[i][1] += a * bv.y;
            }
        }
#pragma unroll
        for (int i = 0; i < 4; i++) {
            int n = rr0 + i;
            Hout[(nb + n) * DD + j0 + 0] = Hg[(nb + n) * DD + j0 + 0] + acc[i][0] + s.sm.B2[j0 + 0];
            Hout[(nb + n) * DD + j0 + 1] = Hg[(nb + n) * DD + j0 + 1] + acc[i][1] + s.sm.B2[j0 + 1];
        }
    }
}

extern "C" void kernel_launch(void* const* d_in, const int* in_sizes, int n_in,
                              void* d_out, int out_size)
{
    const float* X      = (const float*)d_in[1];
    const float* Hg     = (const float*)d_in[2];
    const float* xnw    = (const float*)d_in[4];
    const float* q_w1   = (const float*)d_in[5];
    const float* q_w2   = (const float*)d_in[6];
    const float* kv_w1  = (const float*)d_in[7];
    const float* kv_w2  = (const float*)d_in[8];
    const float* qn_w   = (const float*)d_in[9];
    const float* qn_b   = (const float*)d_in[10];
    const float* kn_w   = (const float*)d_in[11];
    const float* kn_b   = (const float*)d_in[12];
    const float* phx_w1 = (const float*)d_in[13];
    const float* phx_w2 = (const float*)d_in[14];
    const float* phh_w1 = (const float*)d_in[15];
    const float* phh_b1 = (const float*)d_in[16];
    const float* phh_w2 = (const float*)d_in[17];
    const float* phh_b2 = (const float*)d_in[18];

    float* out  = (float*)d_out;
    float* Xout = out;
    float* Hout = out + BB * NN * 3;

    cudaFuncSetAttribute(se3_kernel, cudaFuncAttributeMaxDynamicSharedMemorySize,
                         (int)sizeof(Smem));

    se3_kernel<<<BB, NT, sizeof(Smem)>>>(X, Hg, xnw, q_w1, q_w2, kv_w1, kv_w2,
                                         qn_w, qn_b, kn_w, kn_b,
                                         phx_w1, phx_w2,
                                         phh_w1, phh_b1, phh_w2, phh_b2,
                                         Xout, Hout);
}

// round 17
// speedup vs baseline: 1.4477x; 1.0980x over previous
#include <cuda_runtime.h>
#include <cuda_bf16.h>
#include <math.h>
#include <stdint.h>

#define BB 128
#define NN 64
#define DD 64
#define NT 512

typedef unsigned long long u64;

// ---------------- shared memory layout (~158 KB) ----------------
struct SmallS {
    float Qd[2][128];       // parity-buffered Q rows of active dsts
    float Xn[NN * 4];
    float Rdall[NN * NN];   // rel_dist for every (dst,src) pair  [d*64+s]
    float Alpha[128];
    float Apart[512];       // u partials (alpha^T kv1)
    float PhxPart[512];     // phx partials from VP fragments
    float Spart[12 * 128];  // K row stats partials
    float Wsc[2][2][64];    // parity x dl x col: knw*Qd
    float W1r0[128];
    float PhxW2[DD];
    float QnW[DD], QnB[DD], KnW[DD], KnB[DD];
    float B1[DD], B2[DD];
    float meanNorm;
};

struct Smem {
    __nv_bfloat16 Ahi[128 * 128];   // 32KB @0      iter: A hi | phase0/2: fp32 staging spans Ahi+Alo
    __nv_bfloat16 Alo[128 * 128];   // 32KB @32768
    __nv_bfloat16 Bhi[128 * 128];   // 32KB @65536  rows 0..63: Wk | 64..127: W3   (B in single bf16)
    float P[NN * 128];              // 32KB @98304  (phase0: Q0 staging before P is written)
    SmallS sm;
};

#define OFF_AHI 0u
#define OFF_ALO 32768u
#define OFF_BHI 65536u

// static device scratch
__device__ float g_A[BB * NN * DD];
__device__ float g_Q[BB * NN * DD];

__device__ __forceinline__ float wredsum(float v) {
#pragma unroll
    for (int o = 16; o > 0; o >>= 1) v += __shfl_xor_sync(0xffffffffu, v, o);
    return v;
}
__device__ __forceinline__ float wredmax(float v) {
#pragma unroll
    for (int o = 16; o > 0; o >>= 1) v = fmaxf(v, __shfl_xor_sync(0xffffffffu, v, o));
    return v;
}
// silu via single-MUFU tanh
__device__ __forceinline__ float silu(float x) {
    float t, hx = 0.5f * x;
    asm("tanh.approx.f32 %0, %1;" : "=f"(t) : "f"(hx));
    return fmaf(hx, t, hx);
}

__device__ __forceinline__ uint32_t smem_u32(const void* p) {
    return (uint32_t)__cvta_generic_to_shared(p);
}
__device__ __forceinline__ uint32_t pack_bf2(float a, float b) {
    __nv_bfloat162 h; h.x = __float2bfloat16(a); h.y = __float2bfloat16(b);
    return *(uint32_t*)&h;
}

// ---- mma.sync / ldmatrix (standard PTX) ----
__device__ __forceinline__ void ldm4(uint32_t* r, uint32_t addr) {
    asm volatile("ldmatrix.sync.aligned.m8n8.x4.shared.b16 {%0,%1,%2,%3}, [%4];"
                 : "=r"(r[0]), "=r"(r[1]), "=r"(r[2]), "=r"(r[3]) : "r"(addr));
}
__device__ __forceinline__ void mma16816(float* d, const uint32_t* a, const uint32_t* b) {
    asm volatile(
        "mma.sync.aligned.m16n8k16.row.col.f32.bf16.bf16.f32 "
        "{%0,%1,%2,%3}, {%4,%5,%6,%7}, {%8,%9}, {%0,%1,%2,%3};"
        : "+f"(d[0]), "+f"(d[1]), "+f"(d[2]), "+f"(d[3])
        : "r"(a[0]), "r"(a[1]), "r"(a[2]), "r"(a[3]), "r"(b[0]), "r"(b[1]));
}

// bf16 tile: row-major, 256B rows, 16B-chunk XOR swizzle
__device__ __forceinline__ uint32_t ABaddr(uint32_t base, int r, int ck) {
    return base + ((uint32_t)r << 8) + ((uint32_t)(ck ^ (r & 7)) << 4);
}

// build A = silu(rd*w1row0 + P) as bf16 hi/lo for dst pair d0n, slots [slot0::stride)
__device__ __forceinline__ void build_A(char* smem_raw, SmallS& sm, const float* P,
                                        int d0n, int slot0, int stride) {
    for (int slot = slot0; slot < 2048; slot += stride) {
        int r = slot >> 4, ck = slot & 15, src = r & 63;
        float rd = sm.Rdall[(d0n + (r >> 6)) * 64 + src];
        float4 pa = *(const float4*)&P[src * 128 + ck * 8];
        float4 pc = *(const float4*)&P[src * 128 + ck * 8 + 4];
        float4 wa = *(const float4*)&sm.W1r0[ck * 8];
        float4 wb = *(const float4*)&sm.W1r0[ck * 8 + 4];
        float v[8];
        v[0] = silu(fmaf(rd, wa.x, pa.x)); v[1] = silu(fmaf(rd, wa.y, pa.y));
        v[2] = silu(fmaf(rd, wa.z, pa.z)); v[3] = silu(fmaf(rd, wa.w, pa.w));
        v[4] = silu(fmaf(rd, wb.x, pc.x)); v[5] = silu(fmaf(rd, wb.y, pc.y));
        v[6] = silu(fmaf(rd, wb.z, pc.z)); v[7] = silu(fmaf(rd, wb.w, pc.w));
        uint32_t hi[4], lo[4];
#pragma unroll
        for (int j = 0; j < 4; j++) {
            float x0 = v[2 * j], x1 = v[2 * j + 1];
            __nv_bfloat16 h0 = __float2bfloat16(x0), h1 = __float2bfloat16(x1);
            __nv_bfloat162 hp; hp.x = h0; hp.y = h1;
            hi[j] = *(uint32_t*)&hp;
            lo[j] = pack_bf2(x0 - __bfloat162float(h0), x1 - __bfloat162float(h1));
        }
        *(uint4*)(smem_raw + ABaddr(OFF_AHI, r, ck)) = make_uint4(hi[0], hi[1], hi[2], hi[3]);
        *(uint4*)(smem_raw + ABaddr(OFF_ALO, r, ck)) = make_uint4(lo[0], lo[1], lo[2], lo[3]);
    }
}

__global__ __launch_bounds__(NT, 1)
void se3_kernel(const float* __restrict__ X, const float* __restrict__ Hg,
                const float* __restrict__ xnw,
                const float* __restrict__ q_w1, const float* __restrict__ q_w2,
                const float* __restrict__ kv_w1, const float* __restrict__ kv_w2,
                const float* __restrict__ qn_w, const float* __restrict__ qn_b,
                const float* __restrict__ kn_w, const float* __restrict__ kn_b,
                const float* __restrict__ phx_w1, const float* __restrict__ phx_w2,
                const float* __restrict__ phh_w1, const float* __restrict__ phh_b1,
                const float* __restrict__ phh_w2, const float* __restrict__ phh_b2,
                float* __restrict__ Xout, float* __restrict__ Hout)
{
    extern __shared__ char smem_raw[];
    Smem& s = *reinterpret_cast<Smem*>(smem_raw);

    const int tid  = threadIdx.x;
    const int lane = tid & 31;
    const int wid  = tid >> 5;
    const int nb   = blockIdx.x * NN;
    const uint32_t sb = smem_u32(smem_raw);

    float* AREG = (float*)s.Ahi;          // 16384 fp32 staging (phase 0/2), spans Ahi+Alo
    float* Hs   = (float*)s.Bhi;          // 64x64 (phase 0)
    float* T1   = (float*)s.Bhi + 4096;   // 64x64 (phase 0)
    float* Q0   = s.P;                    // 64x64 (phase 0; P written later)

    // ---------------- phase 0 ----------------
    for (int i = tid; i < NN * DD; i += NT) Hs[i] = Hg[nb * DD + i];
    if (tid < DD) {
        s.sm.QnW[tid] = qn_w[tid];  s.sm.QnB[tid] = qn_b[tid];
        s.sm.KnW[tid] = kn_w[tid];  s.sm.KnB[tid] = kn_b[tid];
        s.sm.PhxW2[tid] = phx_w2[tid];
        s.sm.B1[tid] = phh_b1[tid]; s.sm.B2[tid] = phh_b2[tid];
    }
    if (tid < NN) {
        float x0 = X[(nb + tid) * 3 + 0];
        float x1 = X[(nb + tid) * 3 + 1];
        float x2 = X[(nb + tid) * 3 + 2];
        s.sm.Rdall[tid] = sqrtf(x0 * x0 + x1 * x1 + x2 * x2);   // temp: norms
        s.sm.Xn[tid * 4 + 0] = x0; s.sm.Xn[tid * 4 + 1] = x1; s.sm.Xn[tid * 4 + 2] = x2;
    }
    for (int i = tid; i < DD * DD; i += NT) AREG[i] = q_w1[i];
    __syncthreads();

    if (tid == 0) {
        float m = 0.f;
        for (int i = 0; i < NN; i++) m += s.sm.Rdall[i];
        s.sm.meanNorm = m * (1.f / NN);
    }
    __syncthreads();

    if (tid < NN) {
        float sc = xnw[0] / (s.sm.meanNorm + 1e-5f);
        s.sm.Xn[tid * 4 + 0] *= sc; s.sm.Xn[tid * 4 + 1] *= sc; s.sm.Xn[tid * 4 + 2] *= sc;
    }

    // t1 = silu(H @ q_w1)
    {
        int r0 = wid * 4, j0 = lane * 2;
        float acc[4][2] = {};
#pragma unroll 8
        for (int k = 0; k < DD; k++) {
            float2 bv = *(const float2*)&AREG[k * DD + j0];
#pragma unroll
            for (int i = 0; i < 4; i++) {
                float a = Hs[(r0 + i) * DD + k];
                acc[i][0] += a * bv.x; acc[i][1] += a * bv.y;
            }
        }
#pragma unroll
        for (int i = 0; i < 4; i++) {
            T1[(r0 + i) * DD + j0 + 0] = silu(acc[i][0]);
            T1[(r0 + i) * DD + j0 + 1] = silu(acc[i][1]);
        }
    }
    __syncthreads();
    for (int i = tid; i < DD * DD; i += NT) AREG[i] = q_w2[i];
    // Rdall: full 64x64 rel_dist matrix
    for (int idx = tid; idx < NN * NN; idx += NT) {
        int d = idx >> 6, sc2 = idx & 63;
        float rx = s.sm.Xn[sc2 * 4 + 0] - s.sm.Xn[d * 4 + 0];
        float ry = s.sm.Xn[sc2 * 4 + 1] - s.sm.Xn[d * 4 + 1];
        float rz = s.sm.Xn[sc2 * 4 + 2] - s.sm.Xn[d * 4 + 2];
        s.sm.Rdall[idx] = rx * rx + ry * ry + rz * rz;
    }
    __syncthreads();

    // Q0 = t1 @ q_w2
    {
        int r0 = wid * 4, j0 = lane * 2;
        float acc[4][2] = {};
#pragma unroll 8
        for (int k = 0; k < DD; k++) {
            float2 bv = *(const float2*)&AREG[k * DD + j0];
#pragma unroll
            for (int i = 0; i < 4; i++) {
                float a = T1[(r0 + i) * DD + k];
                acc[i][0] += a * bv.x; acc[i][1] += a * bv.y;
            }
        }
#pragma unroll
        for (int i = 0; i < 4; i++) {
            Q0[(r0 + i) * DD + j0 + 0] = acc[i][0];
            Q0[(r0 + i) * DD + j0 + 1] = acc[i][1];
        }
    }
    __syncthreads();

    // LN(Q0) -> g_Q ; stage kv_w1
#pragma unroll
    for (int i = 0; i < 4; i++) {
        int r = wid * 4 + i;
        float v0 = Q0[r * DD + lane], v1 = Q0[r * DD + 32 + lane];
        float sum = wredsum(v0 + v1);
        float sq  = wredsum(v0 * v0 + v1 * v1);
        float mu  = sum * (1.f / DD);
        float var = sq * (1.f / DD) - mu * mu;
        float rstd = rsqrtf(var + 1e-5f);
        g_Q[(nb + r) * DD + lane]      = (v0 - mu) * rstd * s.sm.QnW[lane]      + s.sm.QnB[lane];
        g_Q[(nb + r) * DD + 32 + lane] = (v1 - mu) * rstd * s.sm.QnW[lane + 32] + s.sm.QnB[lane + 32];
    }
    __syncthreads();
    for (int i = tid; i < 65 * 128; i += NT) AREG[i] = kv_w1[i];
    __syncthreads();

    // P = H @ kv_w1[1:,:]   (overwrites Q0 staging — Q0 already consumed)
    {
        int r0 = wid * 4, c0 = lane * 4;
        float acc[4][4] = {};
#pragma unroll 8
        for (int k = 0; k < DD; k++) {
            float4 bv = *(const float4*)&AREG[(1 + k) * 128 + c0];
#pragma unroll
            for (int i = 0; i < 4; i++) {
                float a = Hs[(r0 + i) * DD + k];
                acc[i][0] += a * bv.x; acc[i][1] += a * bv.y;
                acc[i][2] += a * bv.z; acc[i][3] += a * bv.w;
            }
        }
#pragma unroll
        for (int i = 0; i < 4; i++)
            *(float4*)&s.P[(r0 + i) * 128 + c0] =
                make_float4(acc[i][0], acc[i][1], acc[i][2], acc[i][3]);
    }
    if (tid < 128) s.sm.W1r0[tid] = AREG[tid];
    __syncthreads();

    // stage kv_w2 fp32 into AREG (spans Ahi+Alo, 64KB)
    for (int i = tid; i < 128 * 128; i += NT) AREG[i] = kv_w2[i];
    __syncthreads();

    // Wk = kv_w2[:, :64]^T into B rows 0..63 (bf16, single precision level)
    for (int slot = tid; slot < 1024; slot += NT) {
        int ck = slot >> 6, n = slot & 63;
        uint32_t hi[4];
#pragma unroll
        for (int j = 0; j < 4; j++) {
            float x0 = AREG[(ck * 8 + 2 * j) * 128 + n];
            float x1 = AREG[(ck * 8 + 2 * j + 1) * 128 + n];
            hi[j] = pack_bf2(x0, x1);
        }
        *(uint4*)(smem_raw + ABaddr(OFF_BHI, n, ck)) = make_uint4(hi[0], hi[1], hi[2], hi[3]);
    }
    // W3 = kv_w2[:,64:] @ phx_w1 -> B rows 64..127 (bf16)
    for (int slot = tid; slot < 1024; slot += NT) {
        int c = slot >> 4, ck = slot & 15;
        float acc[8] = {0.f, 0.f, 0.f, 0.f, 0.f, 0.f, 0.f, 0.f};
        for (int jj = 0; jj < 64; jj++) {
            int j = (jj + ck * 4) & 63;
            float w = phx_w1[j * 64 + c];
#pragma unroll
            for (int i = 0; i < 8; i++)
                acc[i] += AREG[(ck * 8 + i) * 128 + 64 + j] * w;
        }
        uint32_t hi[4];
#pragma unroll
        for (int j = 0; j < 4; j++) hi[j] = pack_bf2(acc[2 * j], acc[2 * j + 1]);
        int n = 64 + c;
        *(uint4*)(smem_raw + ABaddr(OFF_BHI, n, ck)) = make_uint4(hi[0], hi[1], hi[2], hi[3]);
    }
    __syncthreads();

    // prologue: Qd/Wsc for p=0 + A tiles for p=0
    if (tid < 128) {
        int r = tid, sIdx = r & 63, dl = r >> 6;
        float qv = g_Q[(nb + dl) * DD + sIdx];
        s.sm.Qd[0][r] = qv;
        s.sm.Wsc[0][dl][sIdx] = s.sm.KnW[sIdx] * qv;
    }
    build_A(smem_raw, s.sm, s.P, 0, tid, NT);
    __syncthreads();

    // ---------------- main loop: 32 iterations, 2 dst nodes each ----------------
    const int wm = wid >> 2, wn = wid & 3;
    const int dlw = wm >> 1;
    const int la15 = lane & 15, lhi = lane >> 4, la7 = lane & 7, lb8 = (lane >> 3) & 1;
    const int rA0 = 32 * wm + la15, rA1 = rA0 + 16;
    const int rBK = 16 * wn + lhi * 8 + la7;
    const int rBV = 64 + 16 * wn + lhi * 8 + la7;
    const int rq = lane >> 2, cq = (lane & 3) << 1;

    for (int p = 0; p < 32; p++) {
        const int d0 = 2 * p;
        const int pb = p & 1;

        // step 3: fused MMA [K | VP], 2-pass bf16 split (Ahi+Alo) x Bhi, 128x128x128
        float accK[16], avp[16];
#pragma unroll
        for (int i = 0; i < 16; i++) { accK[i] = 0.f; avp[i] = 0.f; }
#pragma unroll
        for (int ks = 0; ks < 8; ks++) {
            const int ckA = 2 * ks + lhi, ckB = 2 * ks + lb8;
            uint32_t ah0[4], ah1[4], al0[4], al1[4], bk[4], bv[4];
            ldm4(ah0, ABaddr(sb + OFF_AHI, rA0, ckA));
            ldm4(ah1, ABaddr(sb + OFF_AHI, rA1, ckA));
            ldm4(al0, ABaddr(sb + OFF_ALO, rA0, ckA));
            ldm4(al1, ABaddr(sb + OFF_ALO, rA1, ckA));
            ldm4(bk,  ABaddr(sb + OFF_BHI, rBK, ckB));
            ldm4(bv,  ABaddr(sb + OFF_BHI, rBV, ckB));
#pragma unroll
            for (int j = 0; j < 2; j++) {
                mma16816(&accK[j * 4],     ah0, bk + j * 2);
                mma16816(&accK[8 + j * 4], ah1, bk + j * 2);
                mma16816(&avp[j * 4],      ah0, bv + j * 2);
                mma16816(&avp[8 + j * 4],  ah1, bv + j * 2);
                mma16816(&accK[j * 4],     al0, bk + j * 2);
                mma16816(&accK[8 + j * 4], al1, bk + j * 2);
                mma16816(&avp[j * 4],      al0, bv + j * 2);
                mma16816(&avp[8 + j * 4],  al1, bv + j * 2);
            }
        }

        // step 3b: in-register K row stats + quad-reduce
        {
            float w00 = s.sm.Wsc[pb][dlw][16 * wn + cq];
            float w01 = s.sm.Wsc[pb][dlw][16 * wn + cq + 1];
            float w10 = s.sm.Wsc[pb][dlw][16 * wn + 8 + cq];
            float w11 = s.sm.Wsc[pb][dlw][16 * wn + 8 + cq + 1];
#pragma unroll
            for (int i = 0; i < 2; i++)
#pragma unroll
                for (int h = 0; h < 2; h++) {
                    float a0 = accK[i * 8 + 2 * h],     a1 = accK[i * 8 + 2 * h + 1];
                    float b0 = accK[i * 8 + 4 + 2 * h], b1 = accK[i * 8 + 4 + 2 * h + 1];
                    float sK  = (a0 + a1) + (b0 + b1);
                    float sK2 = fmaf(a0, a0, fmaf(a1, a1, fmaf(b0, b0, b1 * b1)));
                    float sKw = fmaf(a0, w00, fmaf(a1, w01, fmaf(b0, w10, b1 * w11)));
                    sK  += __shfl_xor_sync(0xffffffffu, sK, 1);
                    sK  += __shfl_xor_sync(0xffffffffu, sK, 2);
                    sK2 += __shfl_xor_sync(0xffffffffu, sK2, 1);
                    sK2 += __shfl_xor_sync(0xffffffffu, sK2, 2);
                    sKw += __shfl_xor_sync(0xffffffffu, sKw, 1);
                    sKw += __shfl_xor_sync(0xffffffffu, sKw, 2);
                    if ((lane & 3) == 0) {
                        int r = 32 * wm + 16 * i + rq + 8 * h;
                        s.sm.Spart[(0 * 4 + wn) * 128 + r] = sK;
                        s.sm.Spart[(1 * 4 + wn) * 128 + r] = sK2;
                        s.sm.Spart[(2 * 4 + wn) * 128 + r] = sKw;
                    }
                }
        }
        __syncthreads();   // C: Spart visible; A tiles free for rebuild

        // step 4: warps 0-1 softmax; warps 2-15 build next iteration's A tiles
        if (wid < 2) {
            const int dl = wid, dIdx = d0 + dl;
            float sw  = s.sm.Wsc[pb][dl][lane] + s.sm.Wsc[pb][dl][lane + 32];
            sw = wredsum(sw);
            float sbp = s.sm.KnB[lane]      * s.sm.Qd[pb][dl * 64 + lane]
                      + s.sm.KnB[lane + 32] * s.sm.Qd[pb][dl * 64 + lane + 32];
            sbp = wredsum(sbp);
            const float* Sp = s.sm.Spart;
            float sc[2];
#pragma unroll
            for (int t2 = 0; t2 < 2; t2++) {
                int r = dl * 64 + lane + 32 * t2;
                float sK  = Sp[r]        + Sp[128 + r]  + Sp[256 + r]  + Sp[384 + r];
                float sK2 = Sp[512 + r]  + Sp[640 + r]  + Sp[768 + r]  + Sp[896 + r];
                float sKw = Sp[1024 + r] + Sp[1152 + r] + Sp[1280 + r] + Sp[1408 + r];
                float mu  = sK * (1.f / DD);
                float var = sK2 * (1.f / DD) - mu * mu;
                float rstd = rsqrtf(var + 1e-5f);
                float score = 0.125f * (fmaf(-mu, sw, sKw) * rstd + sbp);
                sc[t2] = (lane + 32 * t2 == dIdx) ? -1e30f : score;
            }
            float m  = wredmax(fmaxf(sc[0], sc[1]));
            float e0 = __expf(sc[0] - m), e1 = __expf(sc[1] - m);
            float ss = wredsum(e0 + e1);
            float inv = __fdividef(1.f, ss);
            s.sm.Alpha[dl * 64 + lane]      = e0 * inv;
            s.sm.Alpha[dl * 64 + 32 + lane] = e1 * inv;
        } else if (p < 31) {
            build_A(smem_raw, s.sm, s.P, d0 + 2, tid - 64, NT - 64);
        }
        __syncthreads();   // D: Alpha + next A tiles ready

        // step 5a: u partials (alpha^T kv1, kv1 recomputed from P)
        {
            int dl = (tid >> 7) & 1, g = tid >> 8, k = tid & 127;
            float w1k = s.sm.W1r0[k];
            const float* rdrow = &s.sm.Rdall[(d0 + dl) * 64];
            float u = 0.f;
            int e0 = g * 32;
#pragma unroll 8
            for (int e = e0; e < e0 + 32; e++) {
                u += s.sm.Alpha[dl * 64 + e] * silu(fmaf(rdrow[e], w1k, s.P[e * 128 + k]));
            }
            s.sm.Apart[tid] = u;
        }
        // step 5b: phx partials from VP fragments
        {
            float w2a[2], w2b[2];
#pragma unroll
            for (int j = 0; j < 2; j++) {
                w2a[j] = s.sm.PhxW2[16 * wn + 8 * j + cq];
                w2b[j] = s.sm.PhxW2[16 * wn + 8 * j + cq + 1];
            }
#pragma unroll
            for (int i = 0; i < 2; i++) {
                int rA = 32 * wm + 16 * i + rq;
                float alA = s.sm.Alpha[rA], alB = s.sm.Alpha[rA + 8];
                float pA = 0.f, pB = 0.f;
#pragma unroll
                for (int j = 0; j < 2; j++) {
                    float* d = &avp[i * 8 + j * 4];
                    pA += silu(alA * d[0]) * w2a[j] + silu(alA * d[1]) * w2b[j];
                    pB += silu(alB * d[2]) * w2a[j] + silu(alB * d[3]) * w2b[j];
                }
                pA += __shfl_xor_sync(0xffffffffu, pA, 1);
                pA += __shfl_xor_sync(0xffffffffu, pA, 2);
                pB += __shfl_xor_sync(0xffffffffu, pB, 1);
                pB += __shfl_xor_sync(0xffffffffu, pB, 2);
                if ((lane & 3) == 0) {
                    s.sm.PhxPart[wn * 128 + rA]     = pA;
                    s.sm.PhxPart[wn * 128 + rA + 8] = pB;
                }
            }
        }
        // step 5c: prefetch Qd/Wsc for next pair (parity buffer)
        if (p < 31 && tid < 128) {
            int r = tid, sIdx = r & 63, dl = r >> 6, dIdx = d0 + 2 + dl;
            float qv = g_Q[(nb + dIdx) * DD + sIdx];
            s.sm.Qd[pb ^ 1][r] = qv;
            s.sm.Wsc[pb ^ 1][dl][sIdx] = s.sm.KnW[sIdx] * qv;
        }
        __syncthreads();   // E

        // step 6a: A = u @ Wv (kv_w2[:,64:] fp32 from L2)
        {
            int out = tid >> 2, q = tid & 3;
            int dl2 = out >> 6, c = out & 63;
            float a = 0.f;
            int k0 = q * 32;
#pragma unroll 8
            for (int k = k0; k < k0 + 32; k++) {
                float uk = s.sm.Apart[dl2 * 128 + k] + s.sm.Apart[256 + dl2 * 128 + k];
                a += uk * kv_w2[k * 128 + 64 + c];
            }
            a += __shfl_xor_sync(0xffffffffu, a, 1);
            a += __shfl_xor_sync(0xffffffffu, a, 2);
            if (q == 0) g_A[(nb + d0 + dl2) * DD + c] = a;
        }
        // step 6b: X_out for both dsts (Rel recomputed from Xn)
        if (wid < 2) {
            int base = wid * 64, dIdx = d0 + wid;
            float dx = s.sm.Xn[dIdx * 4 + 0], dy = s.sm.Xn[dIdx * 4 + 1], dz = s.sm.Xn[dIdx * 4 + 2];
            float p0 = 0.f, p1 = 0.f, p2 = 0.f;
#pragma unroll
            for (int t2 = 0; t2 < 2; t2++) {
                int r = base + lane + 32 * t2, src = (lane + 32 * t2);
                float ph = s.sm.PhxPart[r] + s.sm.PhxPart[128 + r]
                         + s.sm.PhxPart[256 + r] + s.sm.PhxPart[384 + r];
                float rd = s.sm.Rdall[dIdx * 64 + src];
                float wgt = __fdividef(ph, 1.f + sqrtf(rd + 1e-8f));
                p0 += (s.sm.Xn[src * 4 + 0] - dx) * wgt;
                p1 += (s.sm.Xn[src * 4 + 1] - dy) * wgt;
                p2 += (s.sm.Xn[src * 4 + 2] - dz) * wgt;
            }
            p0 = wredsum(p0); p1 = wredsum(p1); p2 = wredsum(p2);
            if (lane == 0) {
                Xout[(nb + dIdx) * 3 + 0] = dx + p0;
                Xout[(nb + dIdx) * 3 + 1] = dy + p1;
                Xout[(nb + dIdx) * 3 + 2] = dz + p2;
            }
        }
        // no end barrier: next-iter smem writes are behind barriers C/D/E
    }
    __syncthreads();

    // ---------------- phase 2: H_out ----------------
    float* Mb = (float*)s.Bhi;
    float* Tb = (float*)s.Bhi + 4096;
    for (int i = tid; i < DD * DD; i += NT) AREG[i]        = phh_w1[i];
    for (int i = tid; i < DD * DD; i += NT) AREG[4096 + i] = phh_w2[i];
    __syncthreads();

    // M = A^2 * H
    for (int i = tid; i < NN * DD; i += NT) {
        float a = g_A[nb * DD + i];
        Mb[i] = a * a * Hg[nb * DD + i];
    }
    __syncthreads();

    // t = silu(M @ phh_w1 + b1)
    {
        int rr0 = wid * 4, j0 = lane * 2;
        float acc[4][2] = {};
#pragma unroll 8
        for (int k = 0; k < DD; k++) {
            float2 bv = *(const float2*)&AREG[k * DD + j0];
#pragma unroll
            for (int i = 0; i < 4; i++) {
                float a = Mb[(rr0 + i) * DD + k];
                acc[i][0] += a * bv.x; acc[i][1] += a * bv.y;
            }
        }
#pragma unroll
        for (int i = 0; i < 4; i++) {
            Tb[(rr0 + i) * DD + j0 + 0] = silu(acc[i][0] + s.sm.B1[j0 + 0]);
            Tb[(rr0 + i) * DD + j0 + 1] = silu(acc[i][1] + s.sm.B1[j0 + 1]);
        }
    }
    __syncthreads();

    // H_out = H + t @ phh_w2 + b2
    {
        int rr0 = wid * 4, j0 = lane * 2;
        float acc[4][2] = {};
#pragma unroll 8
        for (int k = 0; k < DD; k++) {
            float2 bv = *(const float2*)&AREG[4096 + k * DD + j0];
#pragma unroll
            for (int i = 0; i < 4; i++) {
                float a = Tb[(rr0 + i) * DD + k];
                acc[i][0] += a * bv.x; acc[i][1] += a * bv.y;
            }
        }
#pragma unroll
        for (int i = 0; i < 4; i++) {
            int n = rr0 + i;
            Hout[(nb + n) * DD + j0 + 0] = Hg[(nb + n) * DD + j0 + 0] + acc[i][0] + s.sm.B2[j0 + 0];
            Hout[(nb + n) * DD + j0 + 1] = Hg[(nb + n) * DD + j0 + 1] + acc[i][1] + s.sm.B2[j0 + 1];
        }
    }
}

extern "C" void kernel_launch(void* const* d_in, const int* in_sizes, int n_in,
                              void* d_out, int out_size)
{
    const float* X      = (const float*)d_in[1];
    const float* Hg     = (const float*)d_in[2];
    const float* xnw    = (const float*)d_in[4];
    const float* q_w1   = (const float*)d_in[5];
    const float* q_w2   = (const float*)d_in[6];
    const float* kv_w1  = (const float*)d_in[7];
    const float* kv_w2  = (const float*)d_in[8];
    const float* qn_w   = (const float*)d_in[9];
    const float* qn_b   = (const float*)d_in[10];
    const float* kn_w   = (const float*)d_in[11];
    const float* kn_b   = (const float*)d_in[12];
    const float* phx_w1 = (const float*)d_in[13];
    const float* phx_w2 = (const float*)d_in[14];
    const float* phh_w1 = (const float*)d_in[15];
    const float* phh_b1 = (const float*)d_in[16];
    const float* phh_w2 = (const float*)d_in[17];
    const float* phh_b2 = (const float*)d_in[18];

    float* out  = (float*)d_out;
    float* Xout = out;
    float* Hout = out + BB * NN * 3;

    cudaFuncSetAttribute(se3_kernel, cudaFuncAttributeMaxDynamicSharedMemorySize,
                         (int)sizeof(Smem));

    se3_kernel<<<BB, NT, sizeof(Smem)>>>(X, Hg, xnw, q_w1, q_w2, kv_w1, kv_w2,
                                         qn_w, qn_b, kn_w, kn_b,
                                         phx_w1, phx_w2,
                                         phh_w1, phh_b1, phh_w2, phh_b2,
                                         Xout, Hout);
}